// round 14
// baseline (speedup 1.0000x reference)
#include <cuda_runtime.h>
#include <cuda_bf16.h>
#include <math.h>

#define BB   16
#define CIN  20
#define HH   256
#define WW   256
#define WD   64
#define M1   16
#define M2   16
#define NL   4
#define FCH  128
#define COUTC 20
#define NPIX 65536

// ---------------- scratch (device globals; no allocation allowed) -------------
__device__ __nv_bfloat16 g_hh[BB*WD*NPIX];   // activations hi plane (134 MB)
__device__ __nv_bfloat16 g_hl[BB*WD*NPIX];   // activations lo plane
__device__ __nv_bfloat16 g_GxH[BB*WD*HH*32]; // x-DFT result hi: [row=(bc*256+y)][32]
__device__ __nv_bfloat16 g_GxL[BB*WD*HH*32];
__device__ float g_Xft[512*BB*WD*2];         // [mode][bc] complex (mix-coalesced)
__device__ float g_T  [BB*WD*512*2];         // [(b*64+o)*512 + mode] complex
__device__ float g_G2 [BB*WD*HH*32];         // after inverse-y
__device__ float g_Wt [NL*512*4096*2];       // transposed spectral weights [l][mode][io]{re,im}
// bf16 hi/lo basis tables
__device__ __nv_bfloat16 g_bFxT_h[32*256], g_bFxT_l[32*256];   // fwdX B: [t][x]
__device__ __nv_bfloat16 g_bIxB_h[256*32], g_bIxB_l[256*32];   // fuse inv-x B-frag: [x][t]
__device__ __nv_bfloat16 g_bFyA_h[64*256],  g_bFyA_l[64*256];  // fwdY A: [row][y]
__device__ __nv_bfloat16 g_bIyA_h[256*64],  g_bIyA_l[256*64];  // invY A: [y][col]
// pre-split fc0 weights [d][k pad32]
__device__ __nv_bfloat16 g_fc0T_h[WD*32],   g_fc0T_l[WD*32];

__device__ __forceinline__ float gelu_f(float v) {
    return 0.5f * v * (1.0f + erff(v * 0.70710678118654752440f));
}

__device__ __forceinline__ void split_bf(float v, __nv_bfloat16& hi, __nv_bfloat16& lo) {
    hi = __float2bfloat16_rn(v);
    lo = __float2bfloat16_rn(v - __bfloat162float(hi));
}

__device__ __forceinline__ void store_pack(__nv_bfloat16* p, __nv_bfloat16 a, __nv_bfloat16 b) {
    unsigned u = (unsigned)(*(unsigned short*)&a) | ((unsigned)(*(unsigned short*)&b) << 16);
    *(unsigned*)p = u;
}

__device__ __forceinline__ unsigned ld32(const __nv_bfloat16* p) {
    return *(const unsigned*)p;
}

__device__ __forceinline__ void mma_bf16(float c[4], unsigned a0, unsigned a1,
                                         unsigned a2, unsigned a3,
                                         unsigned b0, unsigned b1) {
    asm volatile(
        "mma.sync.aligned.m16n8k16.row.col.f32.bf16.bf16.f32 "
        "{%0,%1,%2,%3}, {%4,%5,%6,%7}, {%8,%9}, {%0,%1,%2,%3};"
        : "+f"(c[0]), "+f"(c[1]), "+f"(c[2]), "+f"(c[3])
        : "r"(a0), "r"(a1), "r"(a2), "r"(a3), "r"(b0), "r"(b1));
}

// ---------------- init basis --------------------------------------------------
__global__ void k_init_basis() {
    int t = blockIdx.x * blockDim.x + threadIdx.x;
    if (t < WW * M2) {
        int x = t >> 4, k = t & 15;
        double ang = (double)(k * x) / 128.0;   // theta / pi
        double s, c; sincospi(ang, &s, &c);
        split_bf((float)c,    g_bFxT_h[(2*k)*256 + x],   g_bFxT_l[(2*k)*256 + x]);
        split_bf((float)(-s), g_bFxT_h[(2*k+1)*256 + x], g_bFxT_l[(2*k+1)*256 + x]);
        double cc = (k == 0) ? 1.0 : 2.0;
        split_bf((float)( cc * c / 65536.0), g_bIxB_h[x*32 + 2*k],   g_bIxB_l[x*32 + 2*k]);
        split_bf((float)(-cc * s / 65536.0), g_bIxB_h[x*32 + 2*k+1], g_bIxB_l[x*32 + 2*k+1]);
    }
    if (t < HH * 32) {
        int y = t >> 5, m = t & 31;
        int ky = (m < 16) ? m : (m + 224);
        double ang = (double)(ky * y) / 128.0;
        double s, c; sincospi(ang, &s, &c);
        split_bf((float)c,    g_bFyA_h[(2*m)*256 + y],   g_bFyA_l[(2*m)*256 + y]);
        split_bf((float)(-s), g_bFyA_h[(2*m+1)*256 + y], g_bFyA_l[(2*m+1)*256 + y]);
        split_bf((float)c,    g_bIyA_h[y*64 + 2*m],      g_bIyA_l[y*64 + 2*m]);
        split_bf((float)s,    g_bIyA_h[y*64 + 2*m+1],    g_bIyA_l[y*64 + 2*m+1]);
    }
}

// ---------------- one-time fc0 weight split (pad K 20->32) --------------------
__global__ void k_wsplit_fc0(const float* __restrict__ fc0w) {
    int t = blockIdx.x * blockDim.x + threadIdx.x;
    if (t < WD * 32) {
        int d = t >> 5, c = t & 31;
        float v = (c < CIN) ? fc0w[d * CIN + c] : 0.f;
        split_bf(v, g_fc0T_h[t], g_fc0T_l[t]);
    }
}

// ---------------- one-time spectral weight transpose -> g_Wt ------------------
__global__ void __launch_bounds__(256) k_wtrans(const float* __restrict__ w1r,
                                                const float* __restrict__ w1i,
                                                const float* __restrict__ w2r,
                                                const float* __restrict__ w2i) {
    __shared__ float sR[64*65], sI[64*65];
    int blk = blockIdx.x;           // 0..511
    int l = blk >> 7;               // layer
    int half = (blk >> 6) & 1;      // 0: w1, 1: w2
    int i = blk & 63;
    const float* wr = half ? w2r : w1r;
    const float* wi = half ? w2i : w1i;
    const float* baseR = wr + ((l*64 + i) * 64) * 256;
    const float* baseI = wi + ((l*64 + i) * 64) * 256;
    for (int mc = 0; mc < 4; mc++) {
        if (mc) __syncthreads();
        for (int l2 = threadIdx.x; l2 < 4096; l2 += 256) {
            int o = l2 >> 6, md = l2 & 63;
            sR[o*65 + md] = baseR[o*256 + mc*64 + md];
            sI[o*65 + md] = baseI[o*256 + mc*64 + md];
        }
        __syncthreads();
        for (int l2 = threadIdx.x; l2 < 4096; l2 += 256) {
            int md = l2 >> 6, o = l2 & 63;
            int gmode = half*256 + mc*64 + md;
            *(float2*)(g_Wt + ((size_t)(l*512 + gmode)*4096 + i*64 + o)*2)
                = make_float2(sR[o*65 + md], sI[o*65 + md]);
        }
    }
}

// ---------------- lift (MMA) + layer-0 forward-x DFT, fused -------------------
#define LEP 264
#define XBK 34
#define LIFT_SMEM (2*(64*LEP)*2 + 64*4)
__global__ void __launch_bounds__(256) k_lift_gx(const float* __restrict__ x,
                                                 const float* __restrict__ b) {
    extern __shared__ char smx[];
    __nv_bfloat16* Eh = (__nv_bfloat16*)smx;          // [64][LEP]
    __nv_bfloat16* El = Eh + 64 * LEP;
    __nv_bfloat16* Bh = Eh;                           // overlay: [256 x][XBK k]
    __nv_bfloat16* Bl = Bh + 256 * XBK;
    float* bsh = (float*)(El + 64 * LEP);             // [64]
    int bb = blockIdx.x >> 8;
    int y  = blockIdx.x & 255;
    int tid = threadIdx.x;

    for (int l = tid; l < 32 * 256; l += 256) {
        int c = l >> 8, xx = l & 255;
        float v = (c < CIN) ? x[(bb * CIN + c) * NPIX + y * 256 + xx] : 0.f;
        split_bf(v, Bh[xx * XBK + c], Bl[xx * XBK + c]);
    }
    if (tid < WD) bsh[tid] = b[tid];
    __syncthreads();

    int wid = tid >> 5, lane = tid & 31;
    int mw = wid & 3, nw = wid >> 2;
    int qr = lane >> 2, qc = lane & 3;
    int r0 = mw * 16 + qr;

    float c1[16][4];
#pragma unroll
    for (int j = 0; j < 16; j++) {
        c1[j][0] = bsh[r0]; c1[j][1] = bsh[r0];
        c1[j][2] = bsh[r0 + 8]; c1[j][3] = bsh[r0 + 8];
    }
#pragma unroll
    for (int k0 = 0; k0 < 2; k0++) {
        int kk = k0 * 16 + qc * 2;
        unsigned ah0 = ld32(g_fc0T_h + r0 * 32 + kk);
        unsigned ah1 = ld32(g_fc0T_h + (r0 + 8) * 32 + kk);
        unsigned ah2 = ld32(g_fc0T_h + r0 * 32 + kk + 8);
        unsigned ah3 = ld32(g_fc0T_h + (r0 + 8) * 32 + kk + 8);
        unsigned al0 = ld32(g_fc0T_l + r0 * 32 + kk);
        unsigned al1 = ld32(g_fc0T_l + (r0 + 8) * 32 + kk);
        unsigned al2 = ld32(g_fc0T_l + r0 * 32 + kk + 8);
        unsigned al3 = ld32(g_fc0T_l + (r0 + 8) * 32 + kk + 8);
#pragma unroll
        for (int j = 0; j < 16; j++) {
            int xc = nw * 128 + j * 8 + qr;
            unsigned bh0 = ld32(Bh + xc * XBK + kk);
            unsigned bh1 = ld32(Bh + xc * XBK + kk + 8);
            unsigned bl0 = ld32(Bl + xc * XBK + kk);
            unsigned bl1 = ld32(Bl + xc * XBK + kk + 8);
            mma_bf16(c1[j], ah0, ah1, ah2, ah3, bh0, bh1);
            mma_bf16(c1[j], ah0, ah1, ah2, ah3, bl0, bl1);
            mma_bf16(c1[j], al0, al1, al2, al3, bh0, bh1);
        }
    }
    __syncthreads();

#pragma unroll
    for (int j = 0; j < 16; j++) {
        int xl = nw * 128 + j * 8 + qc * 2;
        __nv_bfloat16 h0, l0, h1, l1;
        split_bf(c1[j][0], h0, l0); split_bf(c1[j][1], h1, l1);
        store_pack(Eh + r0 * LEP + xl, h0, h1);
        store_pack(El + r0 * LEP + xl, l0, l1);
        split_bf(c1[j][2], h0, l0); split_bf(c1[j][3], h1, l1);
        store_pack(Eh + (r0 + 8) * LEP + xl, h0, h1);
        store_pack(El + (r0 + 8) * LEP + xl, l0, l1);
    }
    __syncthreads();

    for (int l = tid; l < 2048; l += 256) {
        int row = l >> 5, w2 = l & 31;
        *(uint4*)(g_hh + (bb * WD + row) * NPIX + y * 256 + w2 * 8) =
            *(const uint4*)(Eh + row * LEP + w2 * 8);
        *(uint4*)(g_hl + (bb * WD + row) * NPIX + y * 256 + w2 * 8) =
            *(const uint4*)(El + row * LEP + w2 * 8);
    }

    int nt = wid >> 2;
    float cg[2][4];
#pragma unroll
    for (int j = 0; j < 2; j++)
#pragma unroll
        for (int q = 0; q < 4; q++) cg[j][q] = 0.f;
#pragma unroll 4
    for (int k0 = 0; k0 < 16; k0++) {
        int kk = k0 * 16 + qc * 2;
        unsigned ah0 = ld32(Eh + r0 * LEP + kk);
        unsigned ah1 = ld32(Eh + (r0 + 8) * LEP + kk);
        unsigned ah2 = ld32(Eh + r0 * LEP + kk + 8);
        unsigned ah3 = ld32(Eh + (r0 + 8) * LEP + kk + 8);
        unsigned al0 = ld32(El + r0 * LEP + kk);
        unsigned al1 = ld32(El + (r0 + 8) * LEP + kk);
        unsigned al2 = ld32(El + r0 * LEP + kk + 8);
        unsigned al3 = ld32(El + (r0 + 8) * LEP + kk + 8);
#pragma unroll
        for (int j = 0; j < 2; j++) {
            int tc = nt * 16 + j * 8 + qr;
            unsigned bh0 = ld32(g_bFxT_h + tc * 256 + kk);
            unsigned bh1 = ld32(g_bFxT_h + tc * 256 + kk + 8);
            unsigned bl0 = ld32(g_bFxT_l + tc * 256 + kk);
            unsigned bl1 = ld32(g_bFxT_l + tc * 256 + kk + 8);
            mma_bf16(cg[j], ah0, ah1, ah2, ah3, bh0, bh1);
            mma_bf16(cg[j], ah0, ah1, ah2, ah3, bl0, bl1);
            mma_bf16(cg[j], al0, al1, al2, al3, bh0, bh1);
        }
    }
#pragma unroll
    for (int j = 0; j < 2; j++) {
        int tc = nt * 16 + j * 8 + qc * 2;
        int rowA = (bb * WD + r0) * 256 + y;
        int rowB = (bb * WD + r0 + 8) * 256 + y;
        __nv_bfloat16 h0, l0, h1, l1;
        split_bf(cg[j][0], h0, l0); split_bf(cg[j][1], h1, l1);
        store_pack(g_GxH + rowA * 32 + tc, h0, h1);
        store_pack(g_GxL + rowA * 32 + tc, l0, l1);
        split_bf(cg[j][2], h0, l0); split_bf(cg[j][3], h1, l1);
        store_pack(g_GxH + rowB * 32 + tc, h0, h1);
        store_pack(g_GxL + rowB * 32 + tc, l0, l1);
    }
}

// ---------------- forward DFT along y via tensor cores ------------------------
#define YP 264
#define FWDY2_SMEM (2*(32*YP)*2)
__global__ void __launch_bounds__(256) k_fwdY_mma() {
    extern __shared__ char smx[];
    __nv_bfloat16* Bh = (__nv_bfloat16*)smx;     // [32 t][YP y]
    __nv_bfloat16* Bl = Bh + 32 * YP;
    float* Ps = (float*)smx;                     // overlay after mma
    int bc = blockIdx.x;
    int tid = threadIdx.x;
    const __nv_bfloat16* srcH = g_GxH + bc * HH * 32;
    const __nv_bfloat16* srcL = g_GxL + bc * HH * 32;
    for (int l = tid; l < 8192; l += 256) {
        int y = l >> 5, t = l & 31;
        Bh[t * YP + y] = srcH[l];
        Bl[t * YP + y] = srcL[l];
    }
    __syncthreads();
    int wid = tid >> 5, lane = tid & 31;
    int mw = wid & 3, nh = wid >> 2;
    int qr = lane >> 2, qc = lane & 3;
    int r0 = mw * 16 + qr;
    float c[2][4];
#pragma unroll
    for (int j = 0; j < 2; j++)
#pragma unroll
        for (int q = 0; q < 4; q++) c[j][q] = 0.f;
#pragma unroll 4
    for (int k0 = 0; k0 < 16; k0++) {
        int kk = k0 * 16 + qc * 2;
        unsigned ah0 = ld32(g_bFyA_h + r0 * 256 + kk);
        unsigned ah1 = ld32(g_bFyA_h + (r0 + 8) * 256 + kk);
        unsigned ah2 = ld32(g_bFyA_h + r0 * 256 + kk + 8);
        unsigned ah3 = ld32(g_bFyA_h + (r0 + 8) * 256 + kk + 8);
        unsigned al0 = ld32(g_bFyA_l + r0 * 256 + kk);
        unsigned al1 = ld32(g_bFyA_l + (r0 + 8) * 256 + kk);
        unsigned al2 = ld32(g_bFyA_l + r0 * 256 + kk + 8);
        unsigned al3 = ld32(g_bFyA_l + (r0 + 8) * 256 + kk + 8);
#pragma unroll
        for (int j = 0; j < 2; j++) {
            int tc = nh * 16 + j * 8 + qr;
            unsigned bh0 = ld32(Bh + tc * YP + kk);
            unsigned bh1 = ld32(Bh + tc * YP + kk + 8);
            unsigned bl0 = ld32(Bl + tc * YP + kk);
            unsigned bl1 = ld32(Bl + tc * YP + kk + 8);
            mma_bf16(c[j], ah0, ah1, ah2, ah3, bh0, bh1);
            mma_bf16(c[j], ah0, ah1, ah2, ah3, bl0, bl1);
            mma_bf16(c[j], al0, al1, al2, al3, bh0, bh1);
        }
    }
    __syncthreads();
#pragma unroll
    for (int j = 0; j < 2; j++) {
        int cc = nh * 16 + j * 8 + qc * 2;
        Ps[r0 * 33 + cc]           = c[j][0];
        Ps[r0 * 33 + cc + 1]       = c[j][1];
        Ps[(r0 + 8) * 33 + cc]     = c[j][2];
        Ps[(r0 + 8) * 33 + cc + 1] = c[j][3];
    }
    __syncthreads();
    for (int l = tid; l < 512; l += 256) {
        int m = l >> 4, k = l & 15;
        float re = Ps[(2 * m) * 33 + 2 * k]     - Ps[(2 * m + 1) * 33 + 2 * k + 1];
        float im = Ps[(2 * m) * 33 + 2 * k + 1] + Ps[(2 * m + 1) * 33 + 2 * k];
        *(float2*)(g_Xft + (l * 1024 + bc) * 2) = make_float2(re, im);
    }
}

// ---------------- channel mix per mode (coalesced weights via g_Wt) -----------
__global__ void __launch_bounds__(256) k_mix(int layer) {
    __shared__ float Ws[8192];   // [(i*64+o)*2 + c]
    __shared__ float Xs[2048];   // [(b*64+i)*2 + c]
    int mode = blockIdx.x;
    const float* wsrc = g_Wt + (size_t)(layer * 512 + mode) * 8192;
    for (int l = threadIdx.x; l < 8192; l += 256) Ws[l] = wsrc[l];
    const float* xsrc = g_Xft + mode * 2048;
    for (int l = threadIdx.x; l < 2048; l += 256) Xs[l] = xsrc[l];
    __syncthreads();
    int o  = threadIdx.x & 63;
    int bq = threadIdx.x >> 6;
    float ar[4] = {0, 0, 0, 0}, ai[4] = {0, 0, 0, 0};
    for (int i = 0; i < WD; i++) {
        float2 w = *(const float2*)(Ws + (i * 64 + o) * 2);
#pragma unroll
        for (int q = 0; q < 4; q++) {
            float2 xv = *(const float2*)(Xs + ((bq * 4 + q) * 64 + i) * 2);
            ar[q] += xv.x * w.x - xv.y * w.y;
            ai[q] += xv.x * w.y + xv.y * w.x;
        }
    }
#pragma unroll
    for (int q = 0; q < 4; q++) {
        int b = bq * 4 + q;
        *(float2*)(g_T + ((b * 64 + o) * 512 + mode) * 2) = make_float2(ar[q], ai[q]);
    }
}

// ---------------- inverse DFT along y via tensor cores ------------------------
#define IKP 66
#define INVY2_SMEM (1024*4 + 2*(64*IKP)*2)
__global__ void __launch_bounds__(256) k_invY_mma() {
    extern __shared__ char smx[];
    float* Ts = (float*)smx;                             // [1024]
    __nv_bfloat16* Bh = (__nv_bfloat16*)(smx + 4096);    // [64 col][IKP k]
    __nv_bfloat16* Bl = Bh + 64 * IKP;
    int bo = blockIdx.x;
    int tid = threadIdx.x;
    for (int l = tid; l < 1024; l += 256) Ts[l] = g_T[bo * 1024 + l];
    __syncthreads();
    for (int l = tid; l < 4096; l += 256) {
        int col = l >> 6, k = l & 63;
        int k2 = col >> 1, m = k >> 1;
        float Tr = Ts[(m * 16 + k2) * 2];
        float Ti = Ts[(m * 16 + k2) * 2 + 1];
        float v = (col & 1) ? ((k & 1) ? Tr : Ti) : ((k & 1) ? -Ti : Tr);
        split_bf(v, Bh[col * IKP + k], Bl[col * IKP + k]);
    }
    __syncthreads();
    int wid = tid >> 5, lane = tid & 31;
    int qr = lane >> 2, qc = lane & 3;
    float c[2][8][4];
#pragma unroll
    for (int mt = 0; mt < 2; mt++)
#pragma unroll
        for (int j = 0; j < 8; j++)
#pragma unroll
            for (int q = 0; q < 4; q++) c[mt][j][q] = 0.f;
#pragma unroll
    for (int k0 = 0; k0 < 4; k0++) {
        int kk = k0 * 16 + qc * 2;
        unsigned bh0[8], bh1[8], bl0[8], bl1[8];
#pragma unroll
        for (int j = 0; j < 8; j++) {
            int tc = j * 8 + qr;
            bh0[j] = ld32(Bh + tc * IKP + kk);
            bh1[j] = ld32(Bh + tc * IKP + kk + 8);
            bl0[j] = ld32(Bl + tc * IKP + kk);
            bl1[j] = ld32(Bl + tc * IKP + kk + 8);
        }
#pragma unroll
        for (int mt = 0; mt < 2; mt++) {
            int r0 = wid * 32 + mt * 16 + qr;
            unsigned ah0 = ld32(g_bIyA_h + r0 * 64 + kk);
            unsigned ah1 = ld32(g_bIyA_h + (r0 + 8) * 64 + kk);
            unsigned ah2 = ld32(g_bIyA_h + r0 * 64 + kk + 8);
            unsigned ah3 = ld32(g_bIyA_h + (r0 + 8) * 64 + kk + 8);
            unsigned al0 = ld32(g_bIyA_l + r0 * 64 + kk);
            unsigned al1 = ld32(g_bIyA_l + (r0 + 8) * 64 + kk);
            unsigned al2 = ld32(g_bIyA_l + r0 * 64 + kk + 8);
            unsigned al3 = ld32(g_bIyA_l + (r0 + 8) * 64 + kk + 8);
#pragma unroll
            for (int j = 0; j < 8; j++) {
                mma_bf16(c[mt][j], ah0, ah1, ah2, ah3, bh0[j], bh1[j]);
                mma_bf16(c[mt][j], ah0, ah1, ah2, ah3, bl0[j], bl1[j]);
                mma_bf16(c[mt][j], al0, al1, al2, al3, bh0[j], bh1[j]);
            }
        }
    }
    float* dst = g_G2 + bo * 8192;
#pragma unroll
    for (int mt = 0; mt < 2; mt++) {
        int r0 = wid * 32 + mt * 16 + qr;
#pragma unroll
        for (int j = 0; j < 8; j++) {
            int cc = j * 8 + qc * 2;
            *(float2*)(dst + r0 * 32 + cc)       = make_float2(c[mt][j][0], c[mt][j][1]);
            *(float2*)(dst + (r0 + 8) * 32 + cc) = make_float2(c[mt][j][2], c[mt][j][3]);
        }
    }
}

// ---------------- fused layer core + integrated forward-x DFT -----------------
// B smem holds only activation K-rows (k<64); inverse-x basis comes straight
// from global fragment-layout tables. Smem 75.5 -> 58.8 KB (3 blocks/SM).
#define KPAD  98
#define BKP   66
#define EPAD  136
#define BREG  8704   // max(128*BKP, 64*EPAD) elems per plane
#define FUSE2_SMEM ((2*(64*KPAD) + 2*BREG)*2 + 64*4)
__global__ void __launch_bounds__(256) k_fuse_mma(const float* __restrict__ pw_w,
                                                  const float* __restrict__ pw_b,
                                                  int layer, int gelu_gx) {
    extern __shared__ char smx[];
    __nv_bfloat16* Ahs = (__nv_bfloat16*)smx;            // [64][KPAD]
    __nv_bfloat16* Als = Ahs + 64 * KPAD;
    __nv_bfloat16* Bhs = Als + 64 * KPAD;                // [128][BKP] (k<64 only)
    __nv_bfloat16* Bls = Bhs + BREG;
    float* bsh = (float*)(Bls + BREG);
    __nv_bfloat16* Eh = Bhs;                             // epilogue overlay [64][EPAD]
    __nv_bfloat16* El = Bls;

    int bb = blockIdx.x >> 8;
    int y  = blockIdx.x & 255;
    int tid = threadIdx.x;

    for (int l = tid; l < 64 * 64; l += 256) {
        int o = l >> 6, i = l & 63;
        float v = pw_w[(layer * WD + o) * WD + i];
        split_bf(v, Ahs[o * KPAD + i], Als[o * KPAD + i]);
    }
    for (int l = tid; l < 64 * 32; l += 256) {
        int o = l >> 5, t = l & 31;
        float v = g_G2[(bb * WD + o) * 8192 + y * 32 + t];
        split_bf(v, Ahs[o * KPAD + 64 + t], Als[o * KPAD + 64 + t]);
    }
    if (tid < WD) bsh[tid] = pw_b[layer * WD + tid];

    int wid  = tid >> 5, lane = tid & 31;
    int mw   = wid & 3;
    int nw   = wid >> 2;
    int qr   = lane >> 2;
    int qc   = lane & 3;
    int r0   = mw * 16 + qr;

    float cgx[2][4];
#pragma unroll
    for (int j = 0; j < 2; j++)
#pragma unroll
        for (int q = 0; q < 4; q++) cgx[j][q] = 0.f;

    for (int nh = 0; nh < 2; nh++) {
        if (nh) __syncthreads();
        for (int l = tid; l < 64 * 128; l += 256) {
            int k = l >> 7, x = l & 127;
            int gi = (bb * WD + k) * NPIX + y * 256 + nh * 128 + x;
            Bhs[x * BKP + k] = g_hh[gi];
            Bls[x * BKP + k] = g_hl[gi];
        }
        __syncthreads();

        float c[8][4];
#pragma unroll
        for (int j = 0; j < 8; j++) {
            c[j][0] = bsh[r0]; c[j][1] = bsh[r0];
            c[j][2] = bsh[r0 + 8]; c[j][3] = bsh[r0 + 8];
        }
        // K 0..63: activations (B from smem)
#pragma unroll
        for (int k0 = 0; k0 < 4; k0++) {
            int kk = k0 * 16 + qc * 2;
            unsigned ah0 = ld32(Ahs + r0 * KPAD + kk);
            unsigned ah1 = ld32(Ahs + (r0 + 8) * KPAD + kk);
            unsigned ah2 = ld32(Ahs + r0 * KPAD + kk + 8);
            unsigned ah3 = ld32(Ahs + (r0 + 8) * KPAD + kk + 8);
            unsigned al0 = ld32(Als + r0 * KPAD + kk);
            unsigned al1 = ld32(Als + (r0 + 8) * KPAD + kk);
            unsigned al2 = ld32(Als + r0 * KPAD + kk + 8);
            unsigned al3 = ld32(Als + (r0 + 8) * KPAD + kk + 8);
#pragma unroll
            for (int j = 0; j < 8; j++) {
                int xc = nw * 64 + j * 8 + qr;
                unsigned bh0 = ld32(Bhs + xc * BKP + kk);
                unsigned bh1 = ld32(Bhs + xc * BKP + kk + 8);
                unsigned bl0 = ld32(Bls + xc * BKP + kk);
                unsigned bl1 = ld32(Bls + xc * BKP + kk + 8);
                mma_bf16(c[j], ah0, ah1, ah2, ah3, bh0, bh1);
                mma_bf16(c[j], ah0, ah1, ah2, ah3, bl0, bl1);
                mma_bf16(c[j], al0, al1, al2, al3, bh0, bh1);
            }
        }
        // K 64..95: spectral modes (B from global basis table, L1-resident)
#pragma unroll
        for (int k0 = 0; k0 < 2; k0++) {
            int tt = k0 * 16 + qc * 2;
            int kk = 64 + tt;
            unsigned ah0 = ld32(Ahs + r0 * KPAD + kk);
            unsigned ah1 = ld32(Ahs + (r0 + 8) * KPAD + kk);
            unsigned ah2 = ld32(Ahs + r0 * KPAD + kk + 8);
            unsigned ah3 = ld32(Ahs + (r0 + 8) * KPAD + kk + 8);
            unsigned al0 = ld32(Als + r0 * KPAD + kk);
            unsigned al1 = ld32(Als + (r0 + 8) * KPAD + kk);
            unsigned al2 = ld32(Als + r0 * KPAD + kk + 8);
            unsigned al3 = ld32(Als + (r0 + 8) * KPAD + kk + 8);
#pragma unroll
            for (int j = 0; j < 8; j++) {
                int xg = nh * 128 + nw * 64 + j * 8 + qr;
                unsigned bh0 = ld32(g_bIxB_h + xg * 32 + tt);
                unsigned bh1 = ld32(g_bIxB_h + xg * 32 + tt + 8);
                unsigned bl0 = ld32(g_bIxB_l + xg * 32 + tt);
                unsigned bl1 = ld32(g_bIxB_l + xg * 32 + tt + 8);
                mma_bf16(c[j], ah0, ah1, ah2, ah3, bh0, bh1);
                mma_bf16(c[j], ah0, ah1, ah2, ah3, bl0, bl1);
                mma_bf16(c[j], al0, al1, al2, al3, bh0, bh1);
            }
        }

        __syncthreads();   // all warps done reading Bhs/Bls
#pragma unroll
        for (int j = 0; j < 8; j++) {
            int xl = nw * 64 + j * 8 + qc * 2;
            float v0 = c[j][0], v1 = c[j][1], v2 = c[j][2], v3 = c[j][3];
            if (gelu_gx) {
                v0 = gelu_f(v0); v1 = gelu_f(v1);
                v2 = gelu_f(v2); v3 = gelu_f(v3);
            }
            __nv_bfloat16 h0, l0, h1, l1;
            split_bf(v0, h0, l0); split_bf(v1, h1, l1);
            store_pack(Eh + r0 * EPAD + xl, h0, h1);
            store_pack(El + r0 * EPAD + xl, l0, l1);
            split_bf(v2, h0, l0); split_bf(v3, h1, l1);
            store_pack(Eh + (r0 + 8) * EPAD + xl, h0, h1);
            store_pack(El + (r0 + 8) * EPAD + xl, l0, l1);
        }
        __syncthreads();

        if (gelu_gx) {
#pragma unroll
            for (int k0 = 0; k0 < 8; k0++) {
                int kk = k0 * 16 + qc * 2;
                int kb = nh * 128 + kk;
                unsigned ah0 = ld32(Eh + r0 * EPAD + kk);
                unsigned ah1 = ld32(Eh + (r0 + 8) * EPAD + kk);
                unsigned ah2 = ld32(Eh + r0 * EPAD + kk + 8);
                unsigned ah3 = ld32(Eh + (r0 + 8) * EPAD + kk + 8);
                unsigned al0 = ld32(El + r0 * EPAD + kk);
                unsigned al1 = ld32(El + (r0 + 8) * EPAD + kk);
                unsigned al2 = ld32(El + r0 * EPAD + kk + 8);
                unsigned al3 = ld32(El + (r0 + 8) * EPAD + kk + 8);
#pragma unroll
                for (int j = 0; j < 2; j++) {
                    int tc = nw * 16 + j * 8 + qr;
                    unsigned bh0 = ld32(g_bFxT_h + tc * 256 + kb);
                    unsigned bh1 = ld32(g_bFxT_h + tc * 256 + kb + 8);
                    unsigned bl0 = ld32(g_bFxT_l + tc * 256 + kb);
                    unsigned bl1 = ld32(g_bFxT_l + tc * 256 + kb + 8);
                    mma_bf16(cgx[j], ah0, ah1, ah2, ah3, bh0, bh1);
                    mma_bf16(cgx[j], ah0, ah1, ah2, ah3, bl0, bl1);
                    mma_bf16(cgx[j], al0, al1, al2, al3, bh0, bh1);
                }
            }
        }

        for (int l = tid; l < 1024; l += 256) {
            int row = l >> 4, w2 = l & 15;
            *(uint4*)(g_hh + (bb * WD + row) * NPIX + y * 256 + nh * 128 + w2 * 8) =
                *(const uint4*)(Eh + row * EPAD + w2 * 8);
            *(uint4*)(g_hl + (bb * WD + row) * NPIX + y * 256 + nh * 128 + w2 * 8) =
                *(const uint4*)(El + row * EPAD + w2 * 8);
        }
    }

    if (gelu_gx) {
#pragma unroll
        for (int j = 0; j < 2; j++) {
            int tc = nw * 16 + j * 8 + qc * 2;
            int rowA = (bb * WD + r0) * 256 + y;
            int rowB = (bb * WD + r0 + 8) * 256 + y;
            __nv_bfloat16 h0, l0, h1, l1;
            split_bf(cgx[j][0], h0, l0); split_bf(cgx[j][1], h1, l1);
            store_pack(g_GxH + rowA * 32 + tc, h0, h1);
            store_pack(g_GxL + rowA * 32 + tc, l0, l1);
            split_bf(cgx[j][2], h0, l0); split_bf(cgx[j][3], h1, l1);
            store_pack(g_GxH + rowB * 32 + tc, h0, h1);
            store_pack(g_GxL + rowB * 32 + tc, l0, l1);
        }
    }
}

// ---------------- head via tensor cores (round-11) -----------------------------
#define K1P 66
#define K2P 130
#define HP  34
#define HEAD2_SMEM (2*(256*K1P)*2 + 2*(128*K1P)*2 + 2*(32*K2P)*2 + 2*(256*HP)*2 + (128+32)*4)
__global__ void __launch_bounds__(256) k_head_mma(const float* __restrict__ w1,
                                                  const float* __restrict__ b1,
                                                  const float* __restrict__ w2,
                                                  const float* __restrict__ b2,
                                                  float* __restrict__ out) {
    extern __shared__ char smx[];
    __nv_bfloat16* B1h = (__nv_bfloat16*)smx;
    __nv_bfloat16* B1l = B1h + 256 * K1P;
    __nv_bfloat16* A1h = B1l + 256 * K1P;
    __nv_bfloat16* A1l = A1h + 128 * K1P;
    __nv_bfloat16* A2h = A1l + 128 * K1P;
    __nv_bfloat16* A2l = A2h + 32 * K2P;
    __nv_bfloat16* Hh  = A2l + 32 * K2P;
    __nv_bfloat16* Hl  = Hh + 256 * HP;
    float* b1s = (float*)(Hl + 256 * HP);
    float* b2s = b1s + 128;

    int bb = blockIdx.x >> 8;
    int y  = blockIdx.x & 255;
    int tid = threadIdx.x;

    for (int l = tid; l < 64 * 256; l += 256) {
        int i = l >> 8, x = l & 255;
        int gi = (bb * WD + i) * NPIX + y * 256 + x;
        B1h[x * K1P + i] = g_hh[gi];
        B1l[x * K1P + i] = g_hl[gi];
    }
    for (int l = tid; l < 128 * 64; l += 256) {
        int d = l >> 6, i = l & 63;
        split_bf(w1[d * 64 + i], A1h[d * K1P + i], A1l[d * K1P + i]);
    }
    for (int l = tid; l < 32 * 128; l += 256) {
        int e = l >> 7, d = l & 127;
        float v = (e < COUTC) ? w2[e * FCH + d] : 0.f;
        split_bf(v, A2h[e * K2P + d], A2l[e * K2P + d]);
    }
    if (tid < 128) b1s[tid] = b1[tid];
    if (tid < 32)  b2s[tid] = (tid < COUTC) ? b2[tid] : 0.f;
    __syncthreads();

    int wid = tid >> 5, lane = tid & 31;
    int mw = wid & 1;
    int nw = wid >> 1;
    int qr = lane >> 2, qc = lane & 3;
    int r0 = mw * 16 + qr;

    float c2[8][4];
#pragma unroll
    for (int j = 0; j < 8; j++)
#pragma unroll
        for (int q = 0; q < 4; q++) c2[j][q] = 0.f;

    for (int chunk = 0; chunk < 4; chunk++) {
        float c1[8][4];
        int dg0 = chunk * 32 + r0;
#pragma unroll
        for (int j = 0; j < 8; j++) {
            c1[j][0] = b1s[dg0]; c1[j][1] = b1s[dg0];
            c1[j][2] = b1s[dg0 + 8]; c1[j][3] = b1s[dg0 + 8];
        }
#pragma unroll
        for (int k0 = 0; k0 < 4; k0++) {
            int kk = k0 * 16 + qc * 2;
            unsigned ah0 = ld32(A1h + dg0 * K1P + kk);
            unsigned ah1 = ld32(A1h + (dg0 + 8) * K1P + kk);
            unsigned ah2 = ld32(A1h + dg0 * K1P + kk + 8);
            unsigned ah3 = ld32(A1h + (dg0 + 8) * K1P + kk + 8);
            unsigned al0 = ld32(A1l + dg0 * K1P + kk);
            unsigned al1 = ld32(A1l + (dg0 + 8) * K1P + kk);
            unsigned al2 = ld32(A1l + dg0 * K1P + kk + 8);
            unsigned al3 = ld32(A1l + (dg0 + 8) * K1P + kk + 8);
#pragma unroll
            for (int j = 0; j < 8; j++) {
                int xc = nw * 64 + j * 8 + qr;
                unsigned bh0 = ld32(B1h + xc * K1P + kk);
                unsigned bh1 = ld32(B1h + xc * K1P + kk + 8);
                unsigned bl0 = ld32(B1l + xc * K1P + kk);
                unsigned bl1 = ld32(B1l + xc * K1P + kk + 8);
                mma_bf16(c1[j], ah0, ah1, ah2, ah3, bh0, bh1);
                mma_bf16(c1[j], ah0, ah1, ah2, ah3, bl0, bl1);
                mma_bf16(c1[j], al0, al1, al2, al3, bh0, bh1);
            }
        }
#pragma unroll
        for (int j = 0; j < 8; j++) {
            int xc = nw * 64 + j * 8 + qc * 2;
            float v0 = gelu_f(c1[j][0]), v1 = gelu_f(c1[j][1]);
            float v2 = gelu_f(c1[j][2]), v3 = gelu_f(c1[j][3]);
            split_bf(v0, Hh[xc * HP + r0],           Hl[xc * HP + r0]);
            split_bf(v1, Hh[(xc + 1) * HP + r0],     Hl[(xc + 1) * HP + r0]);
            split_bf(v2, Hh[xc * HP + r0 + 8],       Hl[xc * HP + r0 + 8]);
            split_bf(v3, Hh[(xc + 1) * HP + r0 + 8], Hl[(xc + 1) * HP + r0 + 8]);
        }
        __syncthreads();
#pragma unroll
        for (int k0 = 0; k0 < 2; k0++) {
            int kk = k0 * 16 + qc * 2;
            int kg = chunk * 32 + kk;
            unsigned ah0 = ld32(A2h + r0 * K2P + kg);
            unsigned ah1 = ld32(A2h + (r0 + 8) * K2P + kg);
            unsigned ah2 = ld32(A2h + r0 * K2P + kg + 8);
            unsigned ah3 = ld32(A2h + (r0 + 8) * K2P + kg + 8);
            unsigned al0 = ld32(A2l + r0 * K2P + kg);
            unsigned al1 = ld32(A2l + (r0 + 8) * K2P + kg);
            unsigned al2 = ld32(A2l + r0 * K2P + kg + 8);
            unsigned al3 = ld32(A2l + (r0 + 8) * K2P + kg + 8);
#pragma unroll
            for (int j = 0; j < 8; j++) {
                int xc = nw * 64 + j * 8 + qr;
                unsigned bh0 = ld32(Hh + xc * HP + kk);
                unsigned bh1 = ld32(Hh + xc * HP + kk + 8);
                unsigned bl0 = ld32(Hl + xc * HP + kk);
                unsigned bl1 = ld32(Hl + xc * HP + kk + 8);
                mma_bf16(c2[j], ah0, ah1, ah2, ah3, bh0, bh1);
                mma_bf16(c2[j], ah0, ah1, ah2, ah3, bl0, bl1);
                mma_bf16(c2[j], al0, al1, al2, al3, bh0, bh1);
            }
        }
        __syncthreads();
    }

    int e0 = r0, e1 = r0 + 8;
#pragma unroll
    for (int j = 0; j < 8; j++) {
        int xc = nw * 64 + j * 8 + qc * 2;
        if (e0 < COUTC) {
            *(float2*)(out + (bb * COUTC + e0) * NPIX + y * 256 + xc) =
                make_float2(c2[j][0] + b2s[e0], c2[j][1] + b2s[e0]);
        }
        if (e1 < COUTC) {
            *(float2*)(out + (bb * COUTC + e1) * NPIX + y * 256 + xc) =
                make_float2(c2[j][2] + b2s[e1], c2[j][3] + b2s[e1]);
        }
    }
}

// ---------------- launch ------------------------------------------------------
extern "C" void kernel_launch(void* const* d_in, const int* in_sizes, int n_in,
                              void* d_out, int out_size) {
    const float* x    = (const float*)d_in[0];
    const float* w1r  = (const float*)d_in[1];
    const float* w1i  = (const float*)d_in[2];
    const float* w2r  = (const float*)d_in[3];
    const float* w2i  = (const float*)d_in[4];
    const float* pw_w = (const float*)d_in[5];
    const float* pw_b = (const float*)d_in[6];
    const float* fc0w = (const float*)d_in[7];
    const float* fc0b = (const float*)d_in[8];
    const float* fc1w = (const float*)d_in[9];
    const float* fc1b = (const float*)d_in[10];
    const float* fc2w = (const float*)d_in[11];
    const float* fc2b = (const float*)d_in[12];
    float* out = (float*)d_out;

    cudaFuncSetAttribute(k_fuse_mma, cudaFuncAttributeMaxDynamicSharedMemorySize, FUSE2_SMEM);
    cudaFuncSetAttribute(k_lift_gx, cudaFuncAttributeMaxDynamicSharedMemorySize, LIFT_SMEM);
    cudaFuncSetAttribute(k_fwdY_mma, cudaFuncAttributeMaxDynamicSharedMemorySize, FWDY2_SMEM);
    cudaFuncSetAttribute(k_invY_mma, cudaFuncAttributeMaxDynamicSharedMemorySize, INVY2_SMEM);
    cudaFuncSetAttribute(k_head_mma, cudaFuncAttributeMaxDynamicSharedMemorySize, HEAD2_SMEM);

    k_init_basis<<<32, 256>>>();
    k_wsplit_fc0<<<8, 256>>>(fc0w);
    k_wtrans<<<512, 256>>>(w1r, w1i, w2r, w2i);
    k_lift_gx<<<4096, 256, LIFT_SMEM>>>(x, fc0b);   // MMA lift + layer-0 Gx
    for (int l = 0; l < NL; l++) {
        k_fwdY_mma<<<1024, 256, FWDY2_SMEM>>>();
        k_mix<<<512, 256>>>(l);
        k_invY_mma<<<1024, 256, INVY2_SMEM>>>();
        k_fuse_mma<<<4096, 256, FUSE2_SMEM>>>(pw_w, pw_b, l, (l < NL - 1) ? 1 : 0);
    }
    k_head_mma<<<4096, 256, HEAD2_SMEM>>>(fc1w, fc1b, fc2w, fc2b, out);
}

// round 15
// speedup vs baseline: 1.1637x; 1.1637x over previous
#include <cuda_runtime.h>
#include <cuda_bf16.h>
#include <math.h>

#define BB   16
#define CIN  20
#define HH   256
#define WW   256
#define WD   64
#define M1   16
#define M2   16
#define NL   4
#define FCH  128
#define COUTC 20
#define NPIX 65536

// ---------------- scratch (device globals; no allocation allowed) -------------
__device__ __nv_bfloat16 g_hh[BB*WD*NPIX];   // activations hi plane (134 MB)
__device__ __nv_bfloat16 g_hl[BB*WD*NPIX];   // activations lo plane
__device__ __nv_bfloat16 g_GxH[BB*WD*HH*32]; // x-DFT result hi: [row=(bc*256+y)][32]
__device__ __nv_bfloat16 g_GxL[BB*WD*HH*32];
__device__ float g_Xft[512*BB*WD*2];         // [mode][bc] complex (mix-coalesced)
__device__ float g_T  [BB*WD*512*2];         // [(b*64+o)*512 + mode] complex
__device__ float g_G2 [BB*WD*HH*32];         // after inverse-y
__device__ float g_Wt [NL*512*4096*2];       // transposed spectral weights
// bf16 hi/lo basis tables
__device__ __nv_bfloat16 g_bFxT_h[32*256], g_bFxT_l[32*256];   // fwdX B: [t][x]
__device__ __nv_bfloat16 g_bIxT_h[32*256], g_bIxT_l[32*256];   // fuse inv-x: [t][x]
__device__ __nv_bfloat16 g_bFyA_h[64*256],  g_bFyA_l[64*256];  // fwdY A: [row][y]
__device__ __nv_bfloat16 g_bIyA_h[256*64],  g_bIyA_l[256*64];  // invY A: [y][col]
// pre-split fc0 weights [d][k pad32]
__device__ __nv_bfloat16 g_fc0T_h[WD*32],   g_fc0T_l[WD*32];

__device__ __forceinline__ float gelu_f(float v) {
    return 0.5f * v * (1.0f + erff(v * 0.70710678118654752440f));
}

__device__ __forceinline__ void split_bf(float v, __nv_bfloat16& hi, __nv_bfloat16& lo) {
    hi = __float2bfloat16_rn(v);
    lo = __float2bfloat16_rn(v - __bfloat162float(hi));
}

__device__ __forceinline__ void store_pack(__nv_bfloat16* p, __nv_bfloat16 a, __nv_bfloat16 b) {
    unsigned u = (unsigned)(*(unsigned short*)&a) | ((unsigned)(*(unsigned short*)&b) << 16);
    *(unsigned*)p = u;
}

__device__ __forceinline__ unsigned ld32(const __nv_bfloat16* p) {
    return *(const unsigned*)p;
}

__device__ __forceinline__ void mma_bf16(float c[4], unsigned a0, unsigned a1,
                                         unsigned a2, unsigned a3,
                                         unsigned b0, unsigned b1) {
    asm volatile(
        "mma.sync.aligned.m16n8k16.row.col.f32.bf16.bf16.f32 "
        "{%0,%1,%2,%3}, {%4,%5,%6,%7}, {%8,%9}, {%0,%1,%2,%3};"
        : "+f"(c[0]), "+f"(c[1]), "+f"(c[2]), "+f"(c[3])
        : "r"(a0), "r"(a1), "r"(a2), "r"(a3), "r"(b0), "r"(b1));
}

// ---------------- init basis --------------------------------------------------
__global__ void k_init_basis() {
    int t = blockIdx.x * blockDim.x + threadIdx.x;
    if (t < WW * M2) {
        int x = t >> 4, k = t & 15;
        double ang = (double)(k * x) / 128.0;   // theta / pi
        double s, c; sincospi(ang, &s, &c);
        split_bf((float)c,    g_bFxT_h[(2*k)*256 + x],   g_bFxT_l[(2*k)*256 + x]);
        split_bf((float)(-s), g_bFxT_h[(2*k+1)*256 + x], g_bFxT_l[(2*k+1)*256 + x]);
        double cc = (k == 0) ? 1.0 : 2.0;
        split_bf((float)( cc * c / 65536.0), g_bIxT_h[(2*k)*256 + x],   g_bIxT_l[(2*k)*256 + x]);
        split_bf((float)(-cc * s / 65536.0), g_bIxT_h[(2*k+1)*256 + x], g_bIxT_l[(2*k+1)*256 + x]);
    }
    if (t < HH * 32) {
        int y = t >> 5, m = t & 31;
        int ky = (m < 16) ? m : (m + 224);
        double ang = (double)(ky * y) / 128.0;
        double s, c; sincospi(ang, &s, &c);
        split_bf((float)c,    g_bFyA_h[(2*m)*256 + y],   g_bFyA_l[(2*m)*256 + y]);
        split_bf((float)(-s), g_bFyA_h[(2*m+1)*256 + y], g_bFyA_l[(2*m+1)*256 + y]);
        split_bf((float)c,    g_bIyA_h[y*64 + 2*m],      g_bIyA_l[y*64 + 2*m]);
        split_bf((float)s,    g_bIyA_h[y*64 + 2*m+1],    g_bIyA_l[y*64 + 2*m+1]);
    }
}

// ---------------- one-time fc0 weight split (pad K 20->32) --------------------
__global__ void k_wsplit_fc0(const float* __restrict__ fc0w) {
    int t = blockIdx.x * blockDim.x + threadIdx.x;
    if (t < WD * 32) {
        int d = t >> 5, c = t & 31;
        float v = (c < CIN) ? fc0w[d * CIN + c] : 0.f;
        split_bf(v, g_fc0T_h[t], g_fc0T_l[t]);
    }
}

// ---------------- one-time spectral weight transpose -> g_Wt ------------------
__global__ void __launch_bounds__(256) k_wtrans(const float* __restrict__ w1r,
                                                const float* __restrict__ w1i,
                                                const float* __restrict__ w2r,
                                                const float* __restrict__ w2i) {
    __shared__ float sR[64*65], sI[64*65];
    int blk = blockIdx.x;           // 0..511
    int l = blk >> 7;               // layer
    int half = (blk >> 6) & 1;      // 0: w1, 1: w2
    int i = blk & 63;
    const float* wr = half ? w2r : w1r;
    const float* wi = half ? w2i : w1i;
    const float* baseR = wr + ((l*64 + i) * 64) * 256;
    const float* baseI = wi + ((l*64 + i) * 64) * 256;
    for (int mc = 0; mc < 4; mc++) {
        if (mc) __syncthreads();
        for (int l2 = threadIdx.x; l2 < 4096; l2 += 256) {
            int o = l2 >> 6, md = l2 & 63;
            sR[o*65 + md] = baseR[o*256 + mc*64 + md];
            sI[o*65 + md] = baseI[o*256 + mc*64 + md];
        }
        __syncthreads();
        for (int l2 = threadIdx.x; l2 < 4096; l2 += 256) {
            int md = l2 >> 6, o = l2 & 63;
            int gmode = half*256 + mc*64 + md;
            *(float2*)(g_Wt + ((size_t)(l*512 + gmode)*4096 + i*64 + o)*2)
                = make_float2(sR[o*65 + md], sI[o*65 + md]);
        }
    }
}

// ---------------- lift (MMA) + layer-0 forward-x DFT, fused -------------------
#define LEP 264
#define XBK 34
#define LIFT_SMEM (2*(64*LEP)*2 + 64*4)
__global__ void __launch_bounds__(256) k_lift_gx(const float* __restrict__ x,
                                                 const float* __restrict__ b) {
    extern __shared__ char smx[];
    __nv_bfloat16* Eh = (__nv_bfloat16*)smx;          // [64][LEP]
    __nv_bfloat16* El = Eh + 64 * LEP;
    __nv_bfloat16* Bh = Eh;                           // overlay: [256 x][XBK k]
    __nv_bfloat16* Bl = Bh + 256 * XBK;
    float* bsh = (float*)(El + 64 * LEP);             // [64]
    int bb = blockIdx.x >> 8;
    int y  = blockIdx.x & 255;
    int tid = threadIdx.x;

    for (int l = tid; l < 32 * 256; l += 256) {
        int c = l >> 8, xx = l & 255;
        float v = (c < CIN) ? x[(bb * CIN + c) * NPIX + y * 256 + xx] : 0.f;
        split_bf(v, Bh[xx * XBK + c], Bl[xx * XBK + c]);
    }
    if (tid < WD) bsh[tid] = b[tid];
    __syncthreads();

    int wid = tid >> 5, lane = tid & 31;
    int mw = wid & 3, nw = wid >> 2;
    int qr = lane >> 2, qc = lane & 3;
    int r0 = mw * 16 + qr;

    float c1[16][4];
#pragma unroll
    for (int j = 0; j < 16; j++) {
        c1[j][0] = bsh[r0]; c1[j][1] = bsh[r0];
        c1[j][2] = bsh[r0 + 8]; c1[j][3] = bsh[r0 + 8];
    }
#pragma unroll
    for (int k0 = 0; k0 < 2; k0++) {
        int kk = k0 * 16 + qc * 2;
        unsigned ah0 = ld32(g_fc0T_h + r0 * 32 + kk);
        unsigned ah1 = ld32(g_fc0T_h + (r0 + 8) * 32 + kk);
        unsigned ah2 = ld32(g_fc0T_h + r0 * 32 + kk + 8);
        unsigned ah3 = ld32(g_fc0T_h + (r0 + 8) * 32 + kk + 8);
        unsigned al0 = ld32(g_fc0T_l + r0 * 32 + kk);
        unsigned al1 = ld32(g_fc0T_l + (r0 + 8) * 32 + kk);
        unsigned al2 = ld32(g_fc0T_l + r0 * 32 + kk + 8);
        unsigned al3 = ld32(g_fc0T_l + (r0 + 8) * 32 + kk + 8);
#pragma unroll
        for (int j = 0; j < 16; j++) {
            int xc = nw * 128 + j * 8 + qr;
            unsigned bh0 = ld32(Bh + xc * XBK + kk);
            unsigned bh1 = ld32(Bh + xc * XBK + kk + 8);
            unsigned bl0 = ld32(Bl + xc * XBK + kk);
            unsigned bl1 = ld32(Bl + xc * XBK + kk + 8);
            mma_bf16(c1[j], ah0, ah1, ah2, ah3, bh0, bh1);
            mma_bf16(c1[j], ah0, ah1, ah2, ah3, bl0, bl1);
            mma_bf16(c1[j], al0, al1, al2, al3, bh0, bh1);
        }
    }
    __syncthreads();

#pragma unroll
    for (int j = 0; j < 16; j++) {
        int xl = nw * 128 + j * 8 + qc * 2;
        __nv_bfloat16 h0, l0, h1, l1;
        split_bf(c1[j][0], h0, l0); split_bf(c1[j][1], h1, l1);
        store_pack(Eh + r0 * LEP + xl, h0, h1);
        store_pack(El + r0 * LEP + xl, l0, l1);
        split_bf(c1[j][2], h0, l0); split_bf(c1[j][3], h1, l1);
        store_pack(Eh + (r0 + 8) * LEP + xl, h0, h1);
        store_pack(El + (r0 + 8) * LEP + xl, l0, l1);
    }
    __syncthreads();

    for (int l = tid; l < 2048; l += 256) {
        int row = l >> 5, w2 = l & 31;
        *(uint4*)(g_hh + (bb * WD + row) * NPIX + y * 256 + w2 * 8) =
            *(const uint4*)(Eh + row * LEP + w2 * 8);
        *(uint4*)(g_hl + (bb * WD + row) * NPIX + y * 256 + w2 * 8) =
            *(const uint4*)(El + row * LEP + w2 * 8);
    }

    int nt = wid >> 2;
    float cg[2][4];
#pragma unroll
    for (int j = 0; j < 2; j++)
#pragma unroll
        for (int q = 0; q < 4; q++) cg[j][q] = 0.f;
#pragma unroll 4
    for (int k0 = 0; k0 < 16; k0++) {
        int kk = k0 * 16 + qc * 2;
        unsigned ah0 = ld32(Eh + r0 * LEP + kk);
        unsigned ah1 = ld32(Eh + (r0 + 8) * LEP + kk);
        unsigned ah2 = ld32(Eh + r0 * LEP + kk + 8);
        unsigned ah3 = ld32(Eh + (r0 + 8) * LEP + kk + 8);
        unsigned al0 = ld32(El + r0 * LEP + kk);
        unsigned al1 = ld32(El + (r0 + 8) * LEP + kk);
        unsigned al2 = ld32(El + r0 * LEP + kk + 8);
        unsigned al3 = ld32(El + (r0 + 8) * LEP + kk + 8);
#pragma unroll
        for (int j = 0; j < 2; j++) {
            int tc = nt * 16 + j * 8 + qr;
            unsigned bh0 = ld32(g_bFxT_h + tc * 256 + kk);
            unsigned bh1 = ld32(g_bFxT_h + tc * 256 + kk + 8);
            unsigned bl0 = ld32(g_bFxT_l + tc * 256 + kk);
            unsigned bl1 = ld32(g_bFxT_l + tc * 256 + kk + 8);
            mma_bf16(cg[j], ah0, ah1, ah2, ah3, bh0, bh1);
            mma_bf16(cg[j], ah0, ah1, ah2, ah3, bl0, bl1);
            mma_bf16(cg[j], al0, al1, al2, al3, bh0, bh1);
        }
    }
#pragma unroll
    for (int j = 0; j < 2; j++) {
        int tc = nt * 16 + j * 8 + qc * 2;
        int rowA = (bb * WD + r0) * 256 + y;
        int rowB = (bb * WD + r0 + 8) * 256 + y;
        __nv_bfloat16 h0, l0, h1, l1;
        split_bf(cg[j][0], h0, l0); split_bf(cg[j][1], h1, l1);
        store_pack(g_GxH + rowA * 32 + tc, h0, h1);
        store_pack(g_GxL + rowA * 32 + tc, l0, l1);
        split_bf(cg[j][2], h0, l0); split_bf(cg[j][3], h1, l1);
        store_pack(g_GxH + rowB * 32 + tc, h0, h1);
        store_pack(g_GxL + rowB * 32 + tc, l0, l1);
    }
}

// ---------------- forward DFT along y via tensor cores ------------------------
#define YP 264
#define FWDY2_SMEM (2*(32*YP)*2)
__global__ void __launch_bounds__(256) k_fwdY_mma() {
    extern __shared__ char smx[];
    __nv_bfloat16* Bh = (__nv_bfloat16*)smx;     // [32 t][YP y]
    __nv_bfloat16* Bl = Bh + 32 * YP;
    float* Ps = (float*)smx;                     // overlay after mma
    int bc = blockIdx.x;
    int tid = threadIdx.x;
    const __nv_bfloat16* srcH = g_GxH + bc * HH * 32;
    const __nv_bfloat16* srcL = g_GxL + bc * HH * 32;
    for (int l = tid; l < 8192; l += 256) {
        int y = l >> 5, t = l & 31;
        Bh[t * YP + y] = srcH[l];
        Bl[t * YP + y] = srcL[l];
    }
    __syncthreads();
    int wid = tid >> 5, lane = tid & 31;
    int mw = wid & 3, nh = wid >> 2;
    int qr = lane >> 2, qc = lane & 3;
    int r0 = mw * 16 + qr;
    float c[2][4];
#pragma unroll
    for (int j = 0; j < 2; j++)
#pragma unroll
        for (int q = 0; q < 4; q++) c[j][q] = 0.f;
#pragma unroll 4
    for (int k0 = 0; k0 < 16; k0++) {
        int kk = k0 * 16 + qc * 2;
        unsigned ah0 = ld32(g_bFyA_h + r0 * 256 + kk);
        unsigned ah1 = ld32(g_bFyA_h + (r0 + 8) * 256 + kk);
        unsigned ah2 = ld32(g_bFyA_h + r0 * 256 + kk + 8);
        unsigned ah3 = ld32(g_bFyA_h + (r0 + 8) * 256 + kk + 8);
        unsigned al0 = ld32(g_bFyA_l + r0 * 256 + kk);
        unsigned al1 = ld32(g_bFyA_l + (r0 + 8) * 256 + kk);
        unsigned al2 = ld32(g_bFyA_l + r0 * 256 + kk + 8);
        unsigned al3 = ld32(g_bFyA_l + (r0 + 8) * 256 + kk + 8);
#pragma unroll
        for (int j = 0; j < 2; j++) {
            int tc = nh * 16 + j * 8 + qr;
            unsigned bh0 = ld32(Bh + tc * YP + kk);
            unsigned bh1 = ld32(Bh + tc * YP + kk + 8);
            unsigned bl0 = ld32(Bl + tc * YP + kk);
            unsigned bl1 = ld32(Bl + tc * YP + kk + 8);
            mma_bf16(c[j], ah0, ah1, ah2, ah3, bh0, bh1);
            mma_bf16(c[j], ah0, ah1, ah2, ah3, bl0, bl1);
            mma_bf16(c[j], al0, al1, al2, al3, bh0, bh1);
        }
    }
    __syncthreads();
#pragma unroll
    for (int j = 0; j < 2; j++) {
        int cc = nh * 16 + j * 8 + qc * 2;
        Ps[r0 * 33 + cc]           = c[j][0];
        Ps[r0 * 33 + cc + 1]       = c[j][1];
        Ps[(r0 + 8) * 33 + cc]     = c[j][2];
        Ps[(r0 + 8) * 33 + cc + 1] = c[j][3];
    }
    __syncthreads();
    for (int l = tid; l < 512; l += 256) {
        int m = l >> 4, k = l & 15;
        float re = Ps[(2 * m) * 33 + 2 * k]     - Ps[(2 * m + 1) * 33 + 2 * k + 1];
        float im = Ps[(2 * m) * 33 + 2 * k + 1] + Ps[(2 * m + 1) * 33 + 2 * k];
        *(float2*)(g_Xft + (l * 1024 + bc) * 2) = make_float2(re, im);
    }
}

// ---------------- channel mix per mode (coalesced weights via g_Wt) -----------
__global__ void __launch_bounds__(256) k_mix(int layer) {
    __shared__ float Ws[8192];
    __shared__ float Xs[2048];
    int mode = blockIdx.x;
    const float* wsrc = g_Wt + (size_t)(layer * 512 + mode) * 8192;
    for (int l = threadIdx.x; l < 8192; l += 256) Ws[l] = wsrc[l];
    const float* xsrc = g_Xft + mode * 2048;
    for (int l = threadIdx.x; l < 2048; l += 256) Xs[l] = xsrc[l];
    __syncthreads();
    int o  = threadIdx.x & 63;
    int bq = threadIdx.x >> 6;
    float ar[4] = {0, 0, 0, 0}, ai[4] = {0, 0, 0, 0};
    for (int i = 0; i < WD; i++) {
        float2 w = *(const float2*)(Ws + (i * 64 + o) * 2);
#pragma unroll
        for (int q = 0; q < 4; q++) {
            float2 xv = *(const float2*)(Xs + ((bq * 4 + q) * 64 + i) * 2);
            ar[q] += xv.x * w.x - xv.y * w.y;
            ai[q] += xv.x * w.y + xv.y * w.x;
        }
    }
#pragma unroll
    for (int q = 0; q < 4; q++) {
        int b = bq * 4 + q;
        *(float2*)(g_T + ((b * 64 + o) * 512 + mode) * 2) = make_float2(ar[q], ai[q]);
    }
}

// ---------------- inverse DFT along y via tensor cores ------------------------
#define IKP 66
#define INVY2_SMEM (1024*4 + 2*(64*IKP)*2)
__global__ void __launch_bounds__(256) k_invY_mma() {
    extern __shared__ char smx[];
    float* Ts = (float*)smx;                             // [1024]
    __nv_bfloat16* Bh = (__nv_bfloat16*)(smx + 4096);    // [64 col][IKP k]
    __nv_bfloat16* Bl = Bh + 64 * IKP;
    int bo = blockIdx.x;
    int tid = threadIdx.x;
    for (int l = tid; l < 1024; l += 256) Ts[l] = g_T[bo * 1024 + l];
    __syncthreads();
    for (int l = tid; l < 4096; l += 256) {
        int col = l >> 6, k = l & 63;
        int k2 = col >> 1, m = k >> 1;
        float Tr = Ts[(m * 16 + k2) * 2];
        float Ti = Ts[(m * 16 + k2) * 2 + 1];
        float v = (col & 1) ? ((k & 1) ? Tr : Ti) : ((k & 1) ? -Ti : Tr);
        split_bf(v, Bh[col * IKP + k], Bl[col * IKP + k]);
    }
    __syncthreads();
    int wid = tid >> 5, lane = tid & 31;
    int qr = lane >> 2, qc = lane & 3;
    float c[2][8][4];
#pragma unroll
    for (int mt = 0; mt < 2; mt++)
#pragma unroll
        for (int j = 0; j < 8; j++)
#pragma unroll
            for (int q = 0; q < 4; q++) c[mt][j][q] = 0.f;
#pragma unroll
    for (int k0 = 0; k0 < 4; k0++) {
        int kk = k0 * 16 + qc * 2;
        unsigned bh0[8], bh1[8], bl0[8], bl1[8];
#pragma unroll
        for (int j = 0; j < 8; j++) {
            int tc = j * 8 + qr;
            bh0[j] = ld32(Bh + tc * IKP + kk);
            bh1[j] = ld32(Bh + tc * IKP + kk + 8);
            bl0[j] = ld32(Bl + tc * IKP + kk);
            bl1[j] = ld32(Bl + tc * IKP + kk + 8);
        }
#pragma unroll
        for (int mt = 0; mt < 2; mt++) {
            int r0 = wid * 32 + mt * 16 + qr;
            unsigned ah0 = ld32(g_bIyA_h + r0 * 64 + kk);
            unsigned ah1 = ld32(g_bIyA_h + (r0 + 8) * 64 + kk);
            unsigned ah2 = ld32(g_bIyA_h + r0 * 64 + kk + 8);
            unsigned ah3 = ld32(g_bIyA_h + (r0 + 8) * 64 + kk + 8);
            unsigned al0 = ld32(g_bIyA_l + r0 * 64 + kk);
            unsigned al1 = ld32(g_bIyA_l + (r0 + 8) * 64 + kk);
            unsigned al2 = ld32(g_bIyA_l + r0 * 64 + kk + 8);
            unsigned al3 = ld32(g_bIyA_l + (r0 + 8) * 64 + kk + 8);
#pragma unroll
            for (int j = 0; j < 8; j++) {
                mma_bf16(c[mt][j], ah0, ah1, ah2, ah3, bh0[j], bh1[j]);
                mma_bf16(c[mt][j], ah0, ah1, ah2, ah3, bl0[j], bl1[j]);
                mma_bf16(c[mt][j], al0, al1, al2, al3, bh0[j], bh1[j]);
            }
        }
    }
    float* dst = g_G2 + bo * 8192;
#pragma unroll
    for (int mt = 0; mt < 2; mt++) {
        int r0 = wid * 32 + mt * 16 + qr;
#pragma unroll
        for (int j = 0; j < 8; j++) {
            int cc = j * 8 + qc * 2;
            *(float2*)(dst + r0 * 32 + cc)       = make_float2(c[mt][j][0], c[mt][j][1]);
            *(float2*)(dst + (r0 + 8) * 32 + cc) = make_float2(c[mt][j][2], c[mt][j][3]);
        }
    }
}

// ---------------- fused layer core + integrated forward-x DFT (round-11) ------
#define KPAD  98
#define EPAD  136
#define FUSE2_SMEM (2*(64*KPAD)*2 + 2*(128*KPAD)*2 + 64*4)
__global__ void __launch_bounds__(256) k_fuse_mma(const float* __restrict__ pw_w,
                                                  const float* __restrict__ pw_b,
                                                  int layer, int gelu_gx) {
    extern __shared__ char smx[];
    __nv_bfloat16* Ahs = (__nv_bfloat16*)smx;
    __nv_bfloat16* Als = Ahs + 64 * KPAD;
    __nv_bfloat16* Bhs = Als + 64 * KPAD;
    __nv_bfloat16* Bls = Bhs + 128 * KPAD;
    float* bsh = (float*)(Bls + 128 * KPAD);
    __nv_bfloat16* Eh = Bhs;                             // epilogue overlay [64][EPAD]
    __nv_bfloat16* El = Bhs + 64 * EPAD;

    int bb = blockIdx.x >> 8;
    int y  = blockIdx.x & 255;
    int tid = threadIdx.x;

    for (int l = tid; l < 64 * 64; l += 256) {
        int o = l >> 6, i = l & 63;
        float v = pw_w[(layer * WD + o) * WD + i];
        split_bf(v, Ahs[o * KPAD + i], Als[o * KPAD + i]);
    }
    for (int l = tid; l < 64 * 32; l += 256) {
        int o = l >> 5, t = l & 31;
        float v = g_G2[(bb * WD + o) * 8192 + y * 32 + t];
        split_bf(v, Ahs[o * KPAD + 64 + t], Als[o * KPAD + 64 + t]);
    }
    if (tid < WD) bsh[tid] = pw_b[layer * WD + tid];

    int wid  = tid >> 5, lane = tid & 31;
    int mw   = wid & 3;
    int nw   = wid >> 2;
    int qr   = lane >> 2;
    int qc   = lane & 3;
    int r0   = mw * 16 + qr;

    float cgx[2][4];
#pragma unroll
    for (int j = 0; j < 2; j++)
#pragma unroll
        for (int q = 0; q < 4; q++) cgx[j][q] = 0.f;

    for (int nh = 0; nh < 2; nh++) {
        if (nh) __syncthreads();
        for (int l = tid; l < 64 * 128; l += 256) {
            int k = l >> 7, x = l & 127;
            int gi = (bb * WD + k) * NPIX + y * 256 + nh * 128 + x;
            Bhs[x * KPAD + k] = g_hh[gi];
            Bls[x * KPAD + k] = g_hl[gi];
        }
        for (int l = tid; l < 32 * 128; l += 256) {
            int t = l >> 7, x = l & 127;
            Bhs[x * KPAD + 64 + t] = g_bIxT_h[t * 256 + nh * 128 + x];
            Bls[x * KPAD + 64 + t] = g_bIxT_l[t * 256 + nh * 128 + x];
        }
        __syncthreads();

        float c[8][4];
#pragma unroll
        for (int j = 0; j < 8; j++) {
            c[j][0] = bsh[r0]; c[j][1] = bsh[r0];
            c[j][2] = bsh[r0 + 8]; c[j][3] = bsh[r0 + 8];
        }
#pragma unroll
        for (int k0 = 0; k0 < 6; k0++) {
            int kk = k0 * 16 + qc * 2;
            unsigned ah0 = ld32(Ahs + r0 * KPAD + kk);
            unsigned ah1 = ld32(Ahs + (r0 + 8) * KPAD + kk);
            unsigned ah2 = ld32(Ahs + r0 * KPAD + kk + 8);
            unsigned ah3 = ld32(Ahs + (r0 + 8) * KPAD + kk + 8);
            unsigned al0 = ld32(Als + r0 * KPAD + kk);
            unsigned al1 = ld32(Als + (r0 + 8) * KPAD + kk);
            unsigned al2 = ld32(Als + r0 * KPAD + kk + 8);
            unsigned al3 = ld32(Als + (r0 + 8) * KPAD + kk + 8);
#pragma unroll
            for (int j = 0; j < 8; j++) {
                int xc = nw * 64 + j * 8 + qr;
                unsigned bh0 = ld32(Bhs + xc * KPAD + kk);
                unsigned bh1 = ld32(Bhs + xc * KPAD + kk + 8);
                unsigned bl0 = ld32(Bls + xc * KPAD + kk);
                unsigned bl1 = ld32(Bls + xc * KPAD + kk + 8);
                mma_bf16(c[j], ah0, ah1, ah2, ah3, bh0, bh1);
                mma_bf16(c[j], ah0, ah1, ah2, ah3, bl0, bl1);
                mma_bf16(c[j], al0, al1, al2, al3, bh0, bh1);
            }
        }

        __syncthreads();
#pragma unroll
        for (int j = 0; j < 8; j++) {
            int xl = nw * 64 + j * 8 + qc * 2;
            float v0 = c[j][0], v1 = c[j][1], v2 = c[j][2], v3 = c[j][3];
            if (gelu_gx) {
                v0 = gelu_f(v0); v1 = gelu_f(v1);
                v2 = gelu_f(v2); v3 = gelu_f(v3);
            }
            __nv_bfloat16 h0, l0, h1, l1;
            split_bf(v0, h0, l0); split_bf(v1, h1, l1);
            store_pack(Eh + r0 * EPAD + xl, h0, h1);
            store_pack(El + r0 * EPAD + xl, l0, l1);
            split_bf(v2, h0, l0); split_bf(v3, h1, l1);
            store_pack(Eh + (r0 + 8) * EPAD + xl, h0, h1);
            store_pack(El + (r0 + 8) * EPAD + xl, l0, l1);
        }
        __syncthreads();

        if (gelu_gx) {
#pragma unroll
            for (int k0 = 0; k0 < 8; k0++) {
                int kk = k0 * 16 + qc * 2;
                int kb = nh * 128 + kk;
                unsigned ah0 = ld32(Eh + r0 * EPAD + kk);
                unsigned ah1 = ld32(Eh + (r0 + 8) * EPAD + kk);
                unsigned ah2 = ld32(Eh + r0 * EPAD + kk + 8);
                unsigned ah3 = ld32(Eh + (r0 + 8) * EPAD + kk + 8);
                unsigned al0 = ld32(El + r0 * EPAD + kk);
                unsigned al1 = ld32(El + (r0 + 8) * EPAD + kk);
                unsigned al2 = ld32(El + r0 * EPAD + kk + 8);
                unsigned al3 = ld32(El + (r0 + 8) * EPAD + kk + 8);
#pragma unroll
                for (int j = 0; j < 2; j++) {
                    int tc = nw * 16 + j * 8 + qr;
                    unsigned bh0 = ld32(g_bFxT_h + tc * 256 + kb);
                    unsigned bh1 = ld32(g_bFxT_h + tc * 256 + kb + 8);
                    unsigned bl0 = ld32(g_bFxT_l + tc * 256 + kb);
                    unsigned bl1 = ld32(g_bFxT_l + tc * 256 + kb + 8);
                    mma_bf16(cgx[j], ah0, ah1, ah2, ah3, bh0, bh1);
                    mma_bf16(cgx[j], ah0, ah1, ah2, ah3, bl0, bl1);
                    mma_bf16(cgx[j], al0, al1, al2, al3, bh0, bh1);
                }
            }
        }

        for (int l = tid; l < 1024; l += 256) {
            int row = l >> 4, w2 = l & 15;
            *(uint4*)(g_hh + (bb * WD + row) * NPIX + y * 256 + nh * 128 + w2 * 8) =
                *(const uint4*)(Eh + row * EPAD + w2 * 8);
            *(uint4*)(g_hl + (bb * WD + row) * NPIX + y * 256 + nh * 128 + w2 * 8) =
                *(const uint4*)(El + row * EPAD + w2 * 8);
        }
    }

    if (gelu_gx) {
#pragma unroll
        for (int j = 0; j < 2; j++) {
            int tc = nw * 16 + j * 8 + qc * 2;
            int rowA = (bb * WD + r0) * 256 + y;
            int rowB = (bb * WD + r0 + 8) * 256 + y;
            __nv_bfloat16 h0, l0, h1, l1;
            split_bf(cgx[j][0], h0, l0); split_bf(cgx[j][1], h1, l1);
            store_pack(g_GxH + rowA * 32 + tc, h0, h1);
            store_pack(g_GxL + rowA * 32 + tc, l0, l1);
            split_bf(cgx[j][2], h0, l0); split_bf(cgx[j][3], h1, l1);
            store_pack(g_GxH + rowB * 32 + tc, h0, h1);
            store_pack(g_GxL + rowB * 32 + tc, l0, l1);
        }
    }
}

// ---------------- head via tensor cores, two n-halves (102 KB smem) -----------
#define K1P 66
#define K2P 130
#define HP  34
#define HEAD3_SMEM ((2*(128*K1P) + 2*(128*K1P) + 2*(32*K2P) + 2*(128*HP))*2 + 160*4)
__global__ void __launch_bounds__(256) k_head_mma(const float* __restrict__ w1,
                                                  const float* __restrict__ b1,
                                                  const float* __restrict__ w2,
                                                  const float* __restrict__ b2,
                                                  float* __restrict__ out) {
    extern __shared__ char smx[];
    __nv_bfloat16* A1h = (__nv_bfloat16*)smx;        // w1: [128 d][K1P i]
    __nv_bfloat16* A1l = A1h + 128 * K1P;
    __nv_bfloat16* B1h = A1l + 128 * K1P;            // h half: [128 x][K1P i]
    __nv_bfloat16* B1l = B1h + 128 * K1P;
    __nv_bfloat16* A2h = B1l + 128 * K1P;            // w2: [32 e][K2P d]
    __nv_bfloat16* A2l = A2h + 32 * K2P;
    __nv_bfloat16* Hh  = A2l + 32 * K2P;             // hid chunk half: [128 x][HP d]
    __nv_bfloat16* Hl  = Hh + 128 * HP;
    float* b1s = (float*)(Hl + 128 * HP);
    float* b2s = b1s + 128;

    int bb = blockIdx.x >> 8;
    int y  = blockIdx.x & 255;
    int tid = threadIdx.x;

    for (int l = tid; l < 128 * 64; l += 256) {
        int d = l >> 6, i = l & 63;
        split_bf(w1[d * 64 + i], A1h[d * K1P + i], A1l[d * K1P + i]);
    }
    for (int l = tid; l < 32 * 128; l += 256) {
        int e = l >> 7, d = l & 127;
        float v = (e < COUTC) ? w2[e * FCH + d] : 0.f;
        split_bf(v, A2h[e * K2P + d], A2l[e * K2P + d]);
    }
    if (tid < 128) b1s[tid] = b1[tid];
    if (tid < 32)  b2s[tid] = (tid < COUTC) ? b2[tid] : 0.f;

    int wid = tid >> 5, lane = tid & 31;
    int mw = wid & 1;             // 2 m-tiles
    int nw = wid >> 1;            // 4 n-tiles of 32 cols
    int qr = lane >> 2, qc = lane & 3;
    int r0 = mw * 16 + qr;

    for (int nh = 0; nh < 2; nh++) {
        if (nh) __syncthreads();  // prior half's B1/H reads done (chunk-3 sync)
        for (int l = tid; l < 64 * 128; l += 256) {
            int i = l >> 7, x = l & 127;
            int gi = (bb * WD + i) * NPIX + y * 256 + nh * 128 + x;
            B1h[x * K1P + i] = g_hh[gi];
            B1l[x * K1P + i] = g_hl[gi];
        }
        __syncthreads();

        float c2[4][4];
#pragma unroll
        for (int j = 0; j < 4; j++)
#pragma unroll
            for (int q = 0; q < 4; q++) c2[j][q] = 0.f;

        for (int chunk = 0; chunk < 4; chunk++) {
            float c1[4][4];
            int dg0 = chunk * 32 + r0;
#pragma unroll
            for (int j = 0; j < 4; j++) {
                c1[j][0] = b1s[dg0]; c1[j][1] = b1s[dg0];
                c1[j][2] = b1s[dg0 + 8]; c1[j][3] = b1s[dg0 + 8];
            }
#pragma unroll
            for (int k0 = 0; k0 < 4; k0++) {
                int kk = k0 * 16 + qc * 2;
                unsigned ah0 = ld32(A1h + dg0 * K1P + kk);
                unsigned ah1 = ld32(A1h + (dg0 + 8) * K1P + kk);
                unsigned ah2 = ld32(A1h + dg0 * K1P + kk + 8);
                unsigned ah3 = ld32(A1h + (dg0 + 8) * K1P + kk + 8);
                unsigned al0 = ld32(A1l + dg0 * K1P + kk);
                unsigned al1 = ld32(A1l + (dg0 + 8) * K1P + kk);
                unsigned al2 = ld32(A1l + dg0 * K1P + kk + 8);
                unsigned al3 = ld32(A1l + (dg0 + 8) * K1P + kk + 8);
#pragma unroll
                for (int j = 0; j < 4; j++) {
                    int xc = nw * 32 + j * 8 + qr;
                    unsigned bh0 = ld32(B1h + xc * K1P + kk);
                    unsigned bh1 = ld32(B1h + xc * K1P + kk + 8);
                    unsigned bl0 = ld32(B1l + xc * K1P + kk);
                    unsigned bl1 = ld32(B1l + xc * K1P + kk + 8);
                    mma_bf16(c1[j], ah0, ah1, ah2, ah3, bh0, bh1);
                    mma_bf16(c1[j], ah0, ah1, ah2, ah3, bl0, bl1);
                    mma_bf16(c1[j], al0, al1, al2, al3, bh0, bh1);
                }
            }
#pragma unroll
            for (int j = 0; j < 4; j++) {
                int xc = nw * 32 + j * 8 + qc * 2;
                float v0 = gelu_f(c1[j][0]), v1 = gelu_f(c1[j][1]);
                float v2 = gelu_f(c1[j][2]), v3 = gelu_f(c1[j][3]);
                split_bf(v0, Hh[xc * HP + r0],           Hl[xc * HP + r0]);
                split_bf(v1, Hh[(xc + 1) * HP + r0],     Hl[(xc + 1) * HP + r0]);
                split_bf(v2, Hh[xc * HP + r0 + 8],       Hl[xc * HP + r0 + 8]);
                split_bf(v3, Hh[(xc + 1) * HP + r0 + 8], Hl[(xc + 1) * HP + r0 + 8]);
            }
            __syncthreads();
#pragma unroll
            for (int k0 = 0; k0 < 2; k0++) {
                int kk = k0 * 16 + qc * 2;
                int kg = chunk * 32 + kk;
                unsigned ah0 = ld32(A2h + r0 * K2P + kg);
                unsigned ah1 = ld32(A2h + (r0 + 8) * K2P + kg);
                unsigned ah2 = ld32(A2h + r0 * K2P + kg + 8);
                unsigned ah3 = ld32(A2h + (r0 + 8) * K2P + kg + 8);
                unsigned al0 = ld32(A2l + r0 * K2P + kg);
                unsigned al1 = ld32(A2l + (r0 + 8) * K2P + kg);
                unsigned al2 = ld32(A2l + r0 * K2P + kg + 8);
                unsigned al3 = ld32(A2l + (r0 + 8) * K2P + kg + 8);
#pragma unroll
                for (int j = 0; j < 4; j++) {
                    int xc = nw * 32 + j * 8 + qr;
                    unsigned bh0 = ld32(Hh + xc * HP + kk);
                    unsigned bh1 = ld32(Hh + xc * HP + kk + 8);
                    unsigned bl0 = ld32(Hl + xc * HP + kk);
                    unsigned bl1 = ld32(Hl + xc * HP + kk + 8);
                    mma_bf16(c2[j], ah0, ah1, ah2, ah3, bh0, bh1);
                    mma_bf16(c2[j], ah0, ah1, ah2, ah3, bl0, bl1);
                    mma_bf16(c2[j], al0, al1, al2, al3, bh0, bh1);
                }
            }
            __syncthreads();
        }

        int e0 = r0, e1 = r0 + 8;
#pragma unroll
        for (int j = 0; j < 4; j++) {
            int xc = nh * 128 + nw * 32 + j * 8 + qc * 2;
            if (e0 < COUTC) {
                *(float2*)(out + (bb * COUTC + e0) * NPIX + y * 256 + xc) =
                    make_float2(c2[j][0] + b2s[e0], c2[j][1] + b2s[e0]);
            }
            if (e1 < COUTC) {
                *(float2*)(out + (bb * COUTC + e1) * NPIX + y * 256 + xc) =
                    make_float2(c2[j][2] + b2s[e1], c2[j][3] + b2s[e1]);
            }
        }
    }
}

// ---------------- launch ------------------------------------------------------
extern "C" void kernel_launch(void* const* d_in, const int* in_sizes, int n_in,
                              void* d_out, int out_size) {
    const float* x    = (const float*)d_in[0];
    const float* w1r  = (const float*)d_in[1];
    const float* w1i  = (const float*)d_in[2];
    const float* w2r  = (const float*)d_in[3];
    const float* w2i  = (const float*)d_in[4];
    const float* pw_w = (const float*)d_in[5];
    const float* pw_b = (const float*)d_in[6];
    const float* fc0w = (const float*)d_in[7];
    const float* fc0b = (const float*)d_in[8];
    const float* fc1w = (const float*)d_in[9];
    const float* fc1b = (const float*)d_in[10];
    const float* fc2w = (const float*)d_in[11];
    const float* fc2b = (const float*)d_in[12];
    float* out = (float*)d_out;

    cudaFuncSetAttribute(k_fuse_mma, cudaFuncAttributeMaxDynamicSharedMemorySize, FUSE2_SMEM);
    cudaFuncSetAttribute(k_lift_gx, cudaFuncAttributeMaxDynamicSharedMemorySize, LIFT_SMEM);
    cudaFuncSetAttribute(k_fwdY_mma, cudaFuncAttributeMaxDynamicSharedMemorySize, FWDY2_SMEM);
    cudaFuncSetAttribute(k_invY_mma, cudaFuncAttributeMaxDynamicSharedMemorySize, INVY2_SMEM);
    cudaFuncSetAttribute(k_head_mma, cudaFuncAttributeMaxDynamicSharedMemorySize, HEAD3_SMEM);

    k_init_basis<<<32, 256>>>();
    k_wsplit_fc0<<<8, 256>>>(fc0w);
    k_wtrans<<<512, 256>>>(w1r, w1i, w2r, w2i);
    k_lift_gx<<<4096, 256, LIFT_SMEM>>>(x, fc0b);   // MMA lift + layer-0 Gx
    for (int l = 0; l < NL; l++) {
        k_fwdY_mma<<<1024, 256, FWDY2_SMEM>>>();
        k_mix<<<512, 256>>>(l);
        k_invY_mma<<<1024, 256, INVY2_SMEM>>>();
        k_fuse_mma<<<4096, 256, FUSE2_SMEM>>>(pw_w, pw_b, l, (l < NL - 1) ? 1 : 0);
    }
    k_head_mma<<<4096, 256, HEAD3_SMEM>>>(fc1w, fc1b, fc2w, fc2b, out);
}

// round 16
// speedup vs baseline: 1.1656x; 1.0016x over previous
#include <cuda_runtime.h>
#include <cuda_bf16.h>
#include <math.h>

#define BB   16
#define CIN  20
#define HH   256
#define WW   256
#define WD   64
#define M1   16
#define M2   16
#define NL   4
#define FCH  128
#define COUTC 20
#define NPIX 65536

// ---------------- scratch (device globals; no allocation allowed) -------------
__device__ __nv_bfloat16 g_hh[BB*WD*NPIX];   // activations hi plane (134 MB)
__device__ __nv_bfloat16 g_hl[BB*WD*NPIX];   // activations lo plane
__device__ __nv_bfloat16 g_GxH[BB*WD*HH*32]; // x-DFT result hi: [row=(bc*256+y)][32]
__device__ __nv_bfloat16 g_GxL[BB*WD*HH*32];
__device__ float g_Xft[512*BB*WD*2];         // [mode][bc] complex (mix-coalesced)
__device__ float g_T  [BB*WD*512*2];         // [(b*64+o)*512 + mode] complex
__device__ float g_G2 [BB*WD*HH*32];         // after inverse-y
__device__ float g_Wt [NL*512*4096*2];       // transposed spectral weights
// bf16 hi/lo basis tables
__device__ __nv_bfloat16 g_bFxT_h[32*256], g_bFxT_l[32*256];   // fwdX B: [t][x]
__device__ __nv_bfloat16 g_bIxT_h[32*256], g_bIxT_l[32*256];   // fuse inv-x: [t][x]
__device__ __nv_bfloat16 g_bFyA_h[64*256],  g_bFyA_l[64*256];  // fwdY A: [row][y]
__device__ __nv_bfloat16 g_bIyA_h[256*64],  g_bIyA_l[256*64];  // invY A: [y][col]
// pre-split fc0 weights [d][k pad32]
__device__ __nv_bfloat16 g_fc0T_h[WD*32],   g_fc0T_l[WD*32];

__device__ __forceinline__ float gelu_f(float v) {
    return 0.5f * v * (1.0f + erff(v * 0.70710678118654752440f));
}

__device__ __forceinline__ void split_bf(float v, __nv_bfloat16& hi, __nv_bfloat16& lo) {
    hi = __float2bfloat16_rn(v);
    lo = __float2bfloat16_rn(v - __bfloat162float(hi));
}

__device__ __forceinline__ void store_pack(__nv_bfloat16* p, __nv_bfloat16 a, __nv_bfloat16 b) {
    unsigned u = (unsigned)(*(unsigned short*)&a) | ((unsigned)(*(unsigned short*)&b) << 16);
    *(unsigned*)p = u;
}

__device__ __forceinline__ unsigned ld32(const __nv_bfloat16* p) {
    return *(const unsigned*)p;
}

__device__ __forceinline__ void mma_bf16(float c[4], unsigned a0, unsigned a1,
                                         unsigned a2, unsigned a3,
                                         unsigned b0, unsigned b1) {
    asm volatile(
        "mma.sync.aligned.m16n8k16.row.col.f32.bf16.bf16.f32 "
        "{%0,%1,%2,%3}, {%4,%5,%6,%7}, {%8,%9}, {%0,%1,%2,%3};"
        : "+f"(c[0]), "+f"(c[1]), "+f"(c[2]), "+f"(c[3])
        : "r"(a0), "r"(a1), "r"(a2), "r"(a3), "r"(b0), "r"(b1));
}

// ---------------- init basis --------------------------------------------------
__global__ void k_init_basis() {
    int t = blockIdx.x * blockDim.x + threadIdx.x;
    if (t < WW * M2) {
        int x = t >> 4, k = t & 15;
        double ang = (double)(k * x) / 128.0;   // theta / pi
        double s, c; sincospi(ang, &s, &c);
        split_bf((float)c,    g_bFxT_h[(2*k)*256 + x],   g_bFxT_l[(2*k)*256 + x]);
        split_bf((float)(-s), g_bFxT_h[(2*k+1)*256 + x], g_bFxT_l[(2*k+1)*256 + x]);
        double cc = (k == 0) ? 1.0 : 2.0;
        split_bf((float)( cc * c / 65536.0), g_bIxT_h[(2*k)*256 + x],   g_bIxT_l[(2*k)*256 + x]);
        split_bf((float)(-cc * s / 65536.0), g_bIxT_h[(2*k+1)*256 + x], g_bIxT_l[(2*k+1)*256 + x]);
    }
    if (t < HH * 32) {
        int y = t >> 5, m = t & 31;
        int ky = (m < 16) ? m : (m + 224);
        double ang = (double)(ky * y) / 128.0;
        double s, c; sincospi(ang, &s, &c);
        split_bf((float)c,    g_bFyA_h[(2*m)*256 + y],   g_bFyA_l[(2*m)*256 + y]);
        split_bf((float)(-s), g_bFyA_h[(2*m+1)*256 + y], g_bFyA_l[(2*m+1)*256 + y]);
        split_bf((float)c,    g_bIyA_h[y*64 + 2*m],      g_bIyA_l[y*64 + 2*m]);
        split_bf((float)s,    g_bIyA_h[y*64 + 2*m+1],    g_bIyA_l[y*64 + 2*m+1]);
    }
}

// ---------------- one-time fc0 weight split (pad K 20->32) --------------------
__global__ void k_wsplit_fc0(const float* __restrict__ fc0w) {
    int t = blockIdx.x * blockDim.x + threadIdx.x;
    if (t < WD * 32) {
        int d = t >> 5, c = t & 31;
        float v = (c < CIN) ? fc0w[d * CIN + c] : 0.f;
        split_bf(v, g_fc0T_h[t], g_fc0T_l[t]);
    }
}

// ---------------- one-time spectral weight transpose -> g_Wt ------------------
__global__ void __launch_bounds__(256) k_wtrans(const float* __restrict__ w1r,
                                                const float* __restrict__ w1i,
                                                const float* __restrict__ w2r,
                                                const float* __restrict__ w2i) {
    __shared__ float sR[64*65], sI[64*65];
    int blk = blockIdx.x;           // 0..511
    int l = blk >> 7;               // layer
    int half = (blk >> 6) & 1;      // 0: w1, 1: w2
    int i = blk & 63;
    const float* wr = half ? w2r : w1r;
    const float* wi = half ? w2i : w1i;
    const float* baseR = wr + ((l*64 + i) * 64) * 256;
    const float* baseI = wi + ((l*64 + i) * 64) * 256;
    for (int mc = 0; mc < 4; mc++) {
        if (mc) __syncthreads();
        for (int l2 = threadIdx.x; l2 < 4096; l2 += 256) {
            int o = l2 >> 6, md = l2 & 63;
            sR[o*65 + md] = baseR[o*256 + mc*64 + md];
            sI[o*65 + md] = baseI[o*256 + mc*64 + md];
        }
        __syncthreads();
        for (int l2 = threadIdx.x; l2 < 4096; l2 += 256) {
            int md = l2 >> 6, o = l2 & 63;
            int gmode = half*256 + mc*64 + md;
            *(float2*)(g_Wt + ((size_t)(l*512 + gmode)*4096 + i*64 + o)*2)
                = make_float2(sR[o*65 + md], sI[o*65 + md]);
        }
    }
}

// ---------------- lift (MMA) + layer-0 forward-x DFT, fused -------------------
#define LEP 264
#define XBK 34
#define LIFT_SMEM (2*(64*LEP)*2 + 64*4)
__global__ void __launch_bounds__(256) k_lift_gx(const float* __restrict__ x,
                                                 const float* __restrict__ b) {
    extern __shared__ char smx[];
    __nv_bfloat16* Eh = (__nv_bfloat16*)smx;          // [64][LEP]
    __nv_bfloat16* El = Eh + 64 * LEP;
    __nv_bfloat16* Bh = Eh;                           // overlay: [256 x][XBK k]
    __nv_bfloat16* Bl = Bh + 256 * XBK;
    float* bsh = (float*)(El + 64 * LEP);             // [64]
    int bb = blockIdx.x >> 8;
    int y  = blockIdx.x & 255;
    int tid = threadIdx.x;

    for (int l = tid; l < 32 * 256; l += 256) {
        int c = l >> 8, xx = l & 255;
        float v = (c < CIN) ? x[(bb * CIN + c) * NPIX + y * 256 + xx] : 0.f;
        split_bf(v, Bh[xx * XBK + c], Bl[xx * XBK + c]);
    }
    if (tid < WD) bsh[tid] = b[tid];
    __syncthreads();

    int wid = tid >> 5, lane = tid & 31;
    int mw = wid & 3, nw = wid >> 2;
    int qr = lane >> 2, qc = lane & 3;
    int r0 = mw * 16 + qr;

    float c1[16][4];
#pragma unroll
    for (int j = 0; j < 16; j++) {
        c1[j][0] = bsh[r0]; c1[j][1] = bsh[r0];
        c1[j][2] = bsh[r0 + 8]; c1[j][3] = bsh[r0 + 8];
    }
#pragma unroll
    for (int k0 = 0; k0 < 2; k0++) {
        int kk = k0 * 16 + qc * 2;
        unsigned ah0 = ld32(g_fc0T_h + r0 * 32 + kk);
        unsigned ah1 = ld32(g_fc0T_h + (r0 + 8) * 32 + kk);
        unsigned ah2 = ld32(g_fc0T_h + r0 * 32 + kk + 8);
        unsigned ah3 = ld32(g_fc0T_h + (r0 + 8) * 32 + kk + 8);
        unsigned al0 = ld32(g_fc0T_l + r0 * 32 + kk);
        unsigned al1 = ld32(g_fc0T_l + (r0 + 8) * 32 + kk);
        unsigned al2 = ld32(g_fc0T_l + r0 * 32 + kk + 8);
        unsigned al3 = ld32(g_fc0T_l + (r0 + 8) * 32 + kk + 8);
#pragma unroll
        for (int j = 0; j < 16; j++) {
            int xc = nw * 128 + j * 8 + qr;
            unsigned bh0 = ld32(Bh + xc * XBK + kk);
            unsigned bh1 = ld32(Bh + xc * XBK + kk + 8);
            unsigned bl0 = ld32(Bl + xc * XBK + kk);
            unsigned bl1 = ld32(Bl + xc * XBK + kk + 8);
            mma_bf16(c1[j], ah0, ah1, ah2, ah3, bh0, bh1);
            mma_bf16(c1[j], ah0, ah1, ah2, ah3, bl0, bl1);
            mma_bf16(c1[j], al0, al1, al2, al3, bh0, bh1);
        }
    }
    __syncthreads();

#pragma unroll
    for (int j = 0; j < 16; j++) {
        int xl = nw * 128 + j * 8 + qc * 2;
        __nv_bfloat16 h0, l0, h1, l1;
        split_bf(c1[j][0], h0, l0); split_bf(c1[j][1], h1, l1);
        store_pack(Eh + r0 * LEP + xl, h0, h1);
        store_pack(El + r0 * LEP + xl, l0, l1);
        split_bf(c1[j][2], h0, l0); split_bf(c1[j][3], h1, l1);
        store_pack(Eh + (r0 + 8) * LEP + xl, h0, h1);
        store_pack(El + (r0 + 8) * LEP + xl, l0, l1);
    }
    __syncthreads();

    for (int l = tid; l < 2048; l += 256) {
        int row = l >> 5, w2 = l & 31;
        *(uint4*)(g_hh + (bb * WD + row) * NPIX + y * 256 + w2 * 8) =
            *(const uint4*)(Eh + row * LEP + w2 * 8);
        *(uint4*)(g_hl + (bb * WD + row) * NPIX + y * 256 + w2 * 8) =
            *(const uint4*)(El + row * LEP + w2 * 8);
    }

    int nt = wid >> 2;
    float cg[2][4];
#pragma unroll
    for (int j = 0; j < 2; j++)
#pragma unroll
        for (int q = 0; q < 4; q++) cg[j][q] = 0.f;
#pragma unroll 4
    for (int k0 = 0; k0 < 16; k0++) {
        int kk = k0 * 16 + qc * 2;
        unsigned ah0 = ld32(Eh + r0 * LEP + kk);
        unsigned ah1 = ld32(Eh + (r0 + 8) * LEP + kk);
        unsigned ah2 = ld32(Eh + r0 * LEP + kk + 8);
        unsigned ah3 = ld32(Eh + (r0 + 8) * LEP + kk + 8);
        unsigned al0 = ld32(El + r0 * LEP + kk);
        unsigned al1 = ld32(El + (r0 + 8) * LEP + kk);
        unsigned al2 = ld32(El + r0 * LEP + kk + 8);
        unsigned al3 = ld32(El + (r0 + 8) * LEP + kk + 8);
#pragma unroll
        for (int j = 0; j < 2; j++) {
            int tc = nt * 16 + j * 8 + qr;
            unsigned bh0 = ld32(g_bFxT_h + tc * 256 + kk);
            unsigned bh1 = ld32(g_bFxT_h + tc * 256 + kk + 8);
            unsigned bl0 = ld32(g_bFxT_l + tc * 256 + kk);
            unsigned bl1 = ld32(g_bFxT_l + tc * 256 + kk + 8);
            mma_bf16(cg[j], ah0, ah1, ah2, ah3, bh0, bh1);
            mma_bf16(cg[j], ah0, ah1, ah2, ah3, bl0, bl1);
            mma_bf16(cg[j], al0, al1, al2, al3, bh0, bh1);
        }
    }
#pragma unroll
    for (int j = 0; j < 2; j++) {
        int tc = nt * 16 + j * 8 + qc * 2;
        int rowA = (bb * WD + r0) * 256 + y;
        int rowB = (bb * WD + r0 + 8) * 256 + y;
        __nv_bfloat16 h0, l0, h1, l1;
        split_bf(cg[j][0], h0, l0); split_bf(cg[j][1], h1, l1);
        store_pack(g_GxH + rowA * 32 + tc, h0, h1);
        store_pack(g_GxL + rowA * 32 + tc, l0, l1);
        split_bf(cg[j][2], h0, l0); split_bf(cg[j][3], h1, l1);
        store_pack(g_GxH + rowB * 32 + tc, h0, h1);
        store_pack(g_GxL + rowB * 32 + tc, l0, l1);
    }
}

// ---------------- forward DFT along y via tensor cores ------------------------
#define YP 264
#define FWDY2_SMEM (2*(32*YP)*2)
__global__ void __launch_bounds__(256) k_fwdY_mma() {
    extern __shared__ char smx[];
    __nv_bfloat16* Bh = (__nv_bfloat16*)smx;     // [32 t][YP y]
    __nv_bfloat16* Bl = Bh + 32 * YP;
    float* Ps = (float*)smx;                     // overlay after mma
    int bc = blockIdx.x;
    int tid = threadIdx.x;
    const __nv_bfloat16* srcH = g_GxH + bc * HH * 32;
    const __nv_bfloat16* srcL = g_GxL + bc * HH * 32;
    for (int l = tid; l < 8192; l += 256) {
        int y = l >> 5, t = l & 31;
        Bh[t * YP + y] = srcH[l];
        Bl[t * YP + y] = srcL[l];
    }
    __syncthreads();
    int wid = tid >> 5, lane = tid & 31;
    int mw = wid & 3, nh = wid >> 2;
    int qr = lane >> 2, qc = lane & 3;
    int r0 = mw * 16 + qr;
    float c[2][4];
#pragma unroll
    for (int j = 0; j < 2; j++)
#pragma unroll
        for (int q = 0; q < 4; q++) c[j][q] = 0.f;
#pragma unroll 4
    for (int k0 = 0; k0 < 16; k0++) {
        int kk = k0 * 16 + qc * 2;
        unsigned ah0 = ld32(g_bFyA_h + r0 * 256 + kk);
        unsigned ah1 = ld32(g_bFyA_h + (r0 + 8) * 256 + kk);
        unsigned ah2 = ld32(g_bFyA_h + r0 * 256 + kk + 8);
        unsigned ah3 = ld32(g_bFyA_h + (r0 + 8) * 256 + kk + 8);
        unsigned al0 = ld32(g_bFyA_l + r0 * 256 + kk);
        unsigned al1 = ld32(g_bFyA_l + (r0 + 8) * 256 + kk);
        unsigned al2 = ld32(g_bFyA_l + r0 * 256 + kk + 8);
        unsigned al3 = ld32(g_bFyA_l + (r0 + 8) * 256 + kk + 8);
#pragma unroll
        for (int j = 0; j < 2; j++) {
            int tc = nh * 16 + j * 8 + qr;
            unsigned bh0 = ld32(Bh + tc * YP + kk);
            unsigned bh1 = ld32(Bh + tc * YP + kk + 8);
            unsigned bl0 = ld32(Bl + tc * YP + kk);
            unsigned bl1 = ld32(Bl + tc * YP + kk + 8);
            mma_bf16(c[j], ah0, ah1, ah2, ah3, bh0, bh1);
            mma_bf16(c[j], ah0, ah1, ah2, ah3, bl0, bl1);
            mma_bf16(c[j], al0, al1, al2, al3, bh0, bh1);
        }
    }
    __syncthreads();
#pragma unroll
    for (int j = 0; j < 2; j++) {
        int cc = nh * 16 + j * 8 + qc * 2;
        Ps[r0 * 33 + cc]           = c[j][0];
        Ps[r0 * 33 + cc + 1]       = c[j][1];
        Ps[(r0 + 8) * 33 + cc]     = c[j][2];
        Ps[(r0 + 8) * 33 + cc + 1] = c[j][3];
    }
    __syncthreads();
    for (int l = tid; l < 512; l += 256) {
        int m = l >> 4, k = l & 15;
        float re = Ps[(2 * m) * 33 + 2 * k]     - Ps[(2 * m + 1) * 33 + 2 * k + 1];
        float im = Ps[(2 * m) * 33 + 2 * k + 1] + Ps[(2 * m + 1) * 33 + 2 * k];
        *(float2*)(g_Xft + (l * 1024 + bc) * 2) = make_float2(re, im);
    }
}

// ---------------- channel mix per mode (coalesced weights via g_Wt) -----------
__global__ void __launch_bounds__(256) k_mix(int layer) {
    __shared__ float Ws[8192];
    __shared__ float Xs[2048];
    int mode = blockIdx.x;
    const float* wsrc = g_Wt + (size_t)(layer * 512 + mode) * 8192;
    for (int l = threadIdx.x; l < 8192; l += 256) Ws[l] = wsrc[l];
    const float* xsrc = g_Xft + mode * 2048;
    for (int l = threadIdx.x; l < 2048; l += 256) Xs[l] = xsrc[l];
    __syncthreads();
    int o  = threadIdx.x & 63;
    int bq = threadIdx.x >> 6;
    float ar[4] = {0, 0, 0, 0}, ai[4] = {0, 0, 0, 0};
    for (int i = 0; i < WD; i++) {
        float2 w = *(const float2*)(Ws + (i * 64 + o) * 2);
#pragma unroll
        for (int q = 0; q < 4; q++) {
            float2 xv = *(const float2*)(Xs + ((bq * 4 + q) * 64 + i) * 2);
            ar[q] += xv.x * w.x - xv.y * w.y;
            ai[q] += xv.x * w.y + xv.y * w.x;
        }
    }
#pragma unroll
    for (int q = 0; q < 4; q++) {
        int b = bq * 4 + q;
        *(float2*)(g_T + ((b * 64 + o) * 512 + mode) * 2) = make_float2(ar[q], ai[q]);
    }
}

// ---------------- inverse DFT along y via tensor cores ------------------------
#define IKP 66
#define INVY2_SMEM (1024*4 + 2*(64*IKP)*2)
__global__ void __launch_bounds__(256) k_invY_mma() {
    extern __shared__ char smx[];
    float* Ts = (float*)smx;                             // [1024]
    __nv_bfloat16* Bh = (__nv_bfloat16*)(smx + 4096);    // [64 col][IKP k]
    __nv_bfloat16* Bl = Bh + 64 * IKP;
    int bo = blockIdx.x;
    int tid = threadIdx.x;
    for (int l = tid; l < 1024; l += 256) Ts[l] = g_T[bo * 1024 + l];
    __syncthreads();
    for (int l = tid; l < 4096; l += 256) {
        int col = l >> 6, k = l & 63;
        int k2 = col >> 1, m = k >> 1;
        float Tr = Ts[(m * 16 + k2) * 2];
        float Ti = Ts[(m * 16 + k2) * 2 + 1];
        float v = (col & 1) ? ((k & 1) ? Tr : Ti) : ((k & 1) ? -Ti : Tr);
        split_bf(v, Bh[col * IKP + k], Bl[col * IKP + k]);
    }
    __syncthreads();
    int wid = tid >> 5, lane = tid & 31;
    int qr = lane >> 2, qc = lane & 3;
    float c[2][8][4];
#pragma unroll
    for (int mt = 0; mt < 2; mt++)
#pragma unroll
        for (int j = 0; j < 8; j++)
#pragma unroll
            for (int q = 0; q < 4; q++) c[mt][j][q] = 0.f;
#pragma unroll
    for (int k0 = 0; k0 < 4; k0++) {
        int kk = k0 * 16 + qc * 2;
        unsigned bh0[8], bh1[8], bl0[8], bl1[8];
#pragma unroll
        for (int j = 0; j < 8; j++) {
            int tc = j * 8 + qr;
            bh0[j] = ld32(Bh + tc * IKP + kk);
            bh1[j] = ld32(Bh + tc * IKP + kk + 8);
            bl0[j] = ld32(Bl + tc * IKP + kk);
            bl1[j] = ld32(Bl + tc * IKP + kk + 8);
        }
#pragma unroll
        for (int mt = 0; mt < 2; mt++) {
            int r0 = wid * 32 + mt * 16 + qr;
            unsigned ah0 = ld32(g_bIyA_h + r0 * 64 + kk);
            unsigned ah1 = ld32(g_bIyA_h + (r0 + 8) * 64 + kk);
            unsigned ah2 = ld32(g_bIyA_h + r0 * 64 + kk + 8);
            unsigned ah3 = ld32(g_bIyA_h + (r0 + 8) * 64 + kk + 8);
            unsigned al0 = ld32(g_bIyA_l + r0 * 64 + kk);
            unsigned al1 = ld32(g_bIyA_l + (r0 + 8) * 64 + kk);
            unsigned al2 = ld32(g_bIyA_l + r0 * 64 + kk + 8);
            unsigned al3 = ld32(g_bIyA_l + (r0 + 8) * 64 + kk + 8);
#pragma unroll
            for (int j = 0; j < 8; j++) {
                mma_bf16(c[mt][j], ah0, ah1, ah2, ah3, bh0[j], bh1[j]);
                mma_bf16(c[mt][j], ah0, ah1, ah2, ah3, bl0[j], bl1[j]);
                mma_bf16(c[mt][j], al0, al1, al2, al3, bh0[j], bh1[j]);
            }
        }
    }
    float* dst = g_G2 + bo * 8192;
#pragma unroll
    for (int mt = 0; mt < 2; mt++) {
        int r0 = wid * 32 + mt * 16 + qr;
#pragma unroll
        for (int j = 0; j < 8; j++) {
            int cc = j * 8 + qc * 2;
            *(float2*)(dst + r0 * 32 + cc)       = make_float2(c[mt][j][0], c[mt][j][1]);
            *(float2*)(dst + (r0 + 8) * 32 + cc) = make_float2(c[mt][j][2], c[mt][j][3]);
        }
    }
}

// ---------------- fused layer core + integrated forward-x DFT (round-11) ------
#define KPAD  98
#define EPAD  136
#define FUSE2_SMEM (2*(64*KPAD)*2 + 2*(128*KPAD)*2 + 64*4)
__global__ void __launch_bounds__(256) k_fuse_mma(const float* __restrict__ pw_w,
                                                  const float* __restrict__ pw_b,
                                                  int layer, int gelu_gx) {
    extern __shared__ char smx[];
    __nv_bfloat16* Ahs = (__nv_bfloat16*)smx;
    __nv_bfloat16* Als = Ahs + 64 * KPAD;
    __nv_bfloat16* Bhs = Als + 64 * KPAD;
    __nv_bfloat16* Bls = Bhs + 128 * KPAD;
    float* bsh = (float*)(Bls + 128 * KPAD);
    __nv_bfloat16* Eh = Bhs;                             // epilogue overlay [64][EPAD]
    __nv_bfloat16* El = Bhs + 64 * EPAD;

    int bb = blockIdx.x >> 8;
    int y  = blockIdx.x & 255;
    int tid = threadIdx.x;

    for (int l = tid; l < 64 * 64; l += 256) {
        int o = l >> 6, i = l & 63;
        float v = pw_w[(layer * WD + o) * WD + i];
        split_bf(v, Ahs[o * KPAD + i], Als[o * KPAD + i]);
    }
    for (int l = tid; l < 64 * 32; l += 256) {
        int o = l >> 5, t = l & 31;
        float v = g_G2[(bb * WD + o) * 8192 + y * 32 + t];
        split_bf(v, Ahs[o * KPAD + 64 + t], Als[o * KPAD + 64 + t]);
    }
    if (tid < WD) bsh[tid] = pw_b[layer * WD + tid];

    int wid  = tid >> 5, lane = tid & 31;
    int mw   = wid & 3;
    int nw   = wid >> 2;
    int qr   = lane >> 2;
    int qc   = lane & 3;
    int r0   = mw * 16 + qr;

    float cgx[2][4];
#pragma unroll
    for (int j = 0; j < 2; j++)
#pragma unroll
        for (int q = 0; q < 4; q++) cgx[j][q] = 0.f;

    for (int nh = 0; nh < 2; nh++) {
        if (nh) __syncthreads();
        for (int l = tid; l < 64 * 128; l += 256) {
            int k = l >> 7, x = l & 127;
            int gi = (bb * WD + k) * NPIX + y * 256 + nh * 128 + x;
            Bhs[x * KPAD + k] = g_hh[gi];
            Bls[x * KPAD + k] = g_hl[gi];
        }
        for (int l = tid; l < 32 * 128; l += 256) {
            int t = l >> 7, x = l & 127;
            Bhs[x * KPAD + 64 + t] = g_bIxT_h[t * 256 + nh * 128 + x];
            Bls[x * KPAD + 64 + t] = g_bIxT_l[t * 256 + nh * 128 + x];
        }
        __syncthreads();

        float c[8][4];
#pragma unroll
        for (int j = 0; j < 8; j++) {
            c[j][0] = bsh[r0]; c[j][1] = bsh[r0];
            c[j][2] = bsh[r0 + 8]; c[j][3] = bsh[r0 + 8];
        }
#pragma unroll
        for (int k0 = 0; k0 < 6; k0++) {
            int kk = k0 * 16 + qc * 2;
            unsigned ah0 = ld32(Ahs + r0 * KPAD + kk);
            unsigned ah1 = ld32(Ahs + (r0 + 8) * KPAD + kk);
            unsigned ah2 = ld32(Ahs + r0 * KPAD + kk + 8);
            unsigned ah3 = ld32(Ahs + (r0 + 8) * KPAD + kk + 8);
            unsigned al0 = ld32(Als + r0 * KPAD + kk);
            unsigned al1 = ld32(Als + (r0 + 8) * KPAD + kk);
            unsigned al2 = ld32(Als + r0 * KPAD + kk + 8);
            unsigned al3 = ld32(Als + (r0 + 8) * KPAD + kk + 8);
#pragma unroll
            for (int j = 0; j < 8; j++) {
                int xc = nw * 64 + j * 8 + qr;
                unsigned bh0 = ld32(Bhs + xc * KPAD + kk);
                unsigned bh1 = ld32(Bhs + xc * KPAD + kk + 8);
                unsigned bl0 = ld32(Bls + xc * KPAD + kk);
                unsigned bl1 = ld32(Bls + xc * KPAD + kk + 8);
                mma_bf16(c[j], ah0, ah1, ah2, ah3, bh0, bh1);
                mma_bf16(c[j], ah0, ah1, ah2, ah3, bl0, bl1);
                mma_bf16(c[j], al0, al1, al2, al3, bh0, bh1);
            }
        }

        __syncthreads();
#pragma unroll
        for (int j = 0; j < 8; j++) {
            int xl = nw * 64 + j * 8 + qc * 2;
            float v0 = c[j][0], v1 = c[j][1], v2 = c[j][2], v3 = c[j][3];
            if (gelu_gx) {
                v0 = gelu_f(v0); v1 = gelu_f(v1);
                v2 = gelu_f(v2); v3 = gelu_f(v3);
            }
            __nv_bfloat16 h0, l0, h1, l1;
            split_bf(v0, h0, l0); split_bf(v1, h1, l1);
            store_pack(Eh + r0 * EPAD + xl, h0, h1);
            store_pack(El + r0 * EPAD + xl, l0, l1);
            split_bf(v2, h0, l0); split_bf(v3, h1, l1);
            store_pack(Eh + (r0 + 8) * EPAD + xl, h0, h1);
            store_pack(El + (r0 + 8) * EPAD + xl, l0, l1);
        }
        __syncthreads();

        if (gelu_gx) {
#pragma unroll
            for (int k0 = 0; k0 < 8; k0++) {
                int kk = k0 * 16 + qc * 2;
                int kb = nh * 128 + kk;
                unsigned ah0 = ld32(Eh + r0 * EPAD + kk);
                unsigned ah1 = ld32(Eh + (r0 + 8) * EPAD + kk);
                unsigned ah2 = ld32(Eh + r0 * EPAD + kk + 8);
                unsigned ah3 = ld32(Eh + (r0 + 8) * EPAD + kk + 8);
                unsigned al0 = ld32(El + r0 * EPAD + kk);
                unsigned al1 = ld32(El + (r0 + 8) * EPAD + kk);
                unsigned al2 = ld32(El + r0 * EPAD + kk + 8);
                unsigned al3 = ld32(El + (r0 + 8) * EPAD + kk + 8);
#pragma unroll
                for (int j = 0; j < 2; j++) {
                    int tc = nw * 16 + j * 8 + qr;
                    unsigned bh0 = ld32(g_bFxT_h + tc * 256 + kb);
                    unsigned bh1 = ld32(g_bFxT_h + tc * 256 + kb + 8);
                    unsigned bl0 = ld32(g_bFxT_l + tc * 256 + kb);
                    unsigned bl1 = ld32(g_bFxT_l + tc * 256 + kb + 8);
                    mma_bf16(cgx[j], ah0, ah1, ah2, ah3, bh0, bh1);
                    mma_bf16(cgx[j], ah0, ah1, ah2, ah3, bl0, bl1);
                    mma_bf16(cgx[j], al0, al1, al2, al3, bh0, bh1);
                }
            }
        }

        for (int l = tid; l < 1024; l += 256) {
            int row = l >> 4, w2 = l & 15;
            *(uint4*)(g_hh + (bb * WD + row) * NPIX + y * 256 + nh * 128 + w2 * 8) =
                *(const uint4*)(Eh + row * EPAD + w2 * 8);
            *(uint4*)(g_hl + (bb * WD + row) * NPIX + y * 256 + nh * 128 + w2 * 8) =
                *(const uint4*)(El + row * EPAD + w2 * 8);
        }
    }

    if (gelu_gx) {
#pragma unroll
        for (int j = 0; j < 2; j++) {
            int tc = nw * 16 + j * 8 + qc * 2;
            int rowA = (bb * WD + r0) * 256 + y;
            int rowB = (bb * WD + r0 + 8) * 256 + y;
            __nv_bfloat16 h0, l0, h1, l1;
            split_bf(cgx[j][0], h0, l0); split_bf(cgx[j][1], h1, l1);
            store_pack(g_GxH + rowA * 32 + tc, h0, h1);
            store_pack(g_GxL + rowA * 32 + tc, l0, l1);
            split_bf(cgx[j][2], h0, l0); split_bf(cgx[j][3], h1, l1);
            store_pack(g_GxH + rowB * 32 + tc, h0, h1);
            store_pack(g_GxL + rowB * 32 + tc, l0, l1);
        }
    }
}

// ---------------- head via tensor cores, two n-halves (102 KB smem) -----------
#define K1P 66
#define K2P 130
#define HP  34
#define HEAD3_SMEM ((2*(128*K1P) + 2*(128*K1P) + 2*(32*K2P) + 2*(128*HP))*2 + 160*4)
__global__ void __launch_bounds__(256) k_head_mma(const float* __restrict__ w1,
                                                  const float* __restrict__ b1,
                                                  const float* __restrict__ w2,
                                                  const float* __restrict__ b2,
                                                  float* __restrict__ out) {
    extern __shared__ char smx[];
    __nv_bfloat16* A1h = (__nv_bfloat16*)smx;        // w1: [128 d][K1P i]
    __nv_bfloat16* A1l = A1h + 128 * K1P;
    __nv_bfloat16* B1h = A1l + 128 * K1P;            // h half: [128 x][K1P i]
    __nv_bfloat16* B1l = B1h + 128 * K1P;
    __nv_bfloat16* A2h = B1l + 128 * K1P;            // w2: [32 e][K2P d]
    __nv_bfloat16* A2l = A2h + 32 * K2P;
    __nv_bfloat16* Hh  = A2l + 32 * K2P;             // hid chunk half: [128 x][HP d]
    __nv_bfloat16* Hl  = Hh + 128 * HP;
    float* b1s = (float*)(Hl + 128 * HP);
    float* b2s = b1s + 128;

    int bb = blockIdx.x >> 8;
    int y  = blockIdx.x & 255;
    int tid = threadIdx.x;

    for (int l = tid; l < 128 * 64; l += 256) {
        int d = l >> 6, i = l & 63;
        split_bf(w1[d * 64 + i], A1h[d * K1P + i], A1l[d * K1P + i]);
    }
    for (int l = tid; l < 32 * 128; l += 256) {
        int e = l >> 7, d = l & 127;
        float v = (e < COUTC) ? w2[e * FCH + d] : 0.f;
        split_bf(v, A2h[e * K2P + d], A2l[e * K2P + d]);
    }
    if (tid < 128) b1s[tid] = b1[tid];
    if (tid < 32)  b2s[tid] = (tid < COUTC) ? b2[tid] : 0.f;

    int wid = tid >> 5, lane = tid & 31;
    int mw = wid & 1;             // 2 m-tiles
    int nw = wid >> 1;            // 4 n-tiles of 32 cols
    int qr = lane >> 2, qc = lane & 3;
    int r0 = mw * 16 + qr;

    for (int nh = 0; nh < 2; nh++) {
        if (nh) __syncthreads();  // prior half's B1/H reads done (chunk-3 sync)
        for (int l = tid; l < 64 * 128; l += 256) {
            int i = l >> 7, x = l & 127;
            int gi = (bb * WD + i) * NPIX + y * 256 + nh * 128 + x;
            B1h[x * K1P + i] = g_hh[gi];
            B1l[x * K1P + i] = g_hl[gi];
        }
        __syncthreads();

        float c2[4][4];
#pragma unroll
        for (int j = 0; j < 4; j++)
#pragma unroll
            for (int q = 0; q < 4; q++) c2[j][q] = 0.f;

        for (int chunk = 0; chunk < 4; chunk++) {
            float c1[4][4];
            int dg0 = chunk * 32 + r0;
#pragma unroll
            for (int j = 0; j < 4; j++) {
                c1[j][0] = b1s[dg0]; c1[j][1] = b1s[dg0];
                c1[j][2] = b1s[dg0 + 8]; c1[j][3] = b1s[dg0 + 8];
            }
#pragma unroll
            for (int k0 = 0; k0 < 4; k0++) {
                int kk = k0 * 16 + qc * 2;
                unsigned ah0 = ld32(A1h + dg0 * K1P + kk);
                unsigned ah1 = ld32(A1h + (dg0 + 8) * K1P + kk);
                unsigned ah2 = ld32(A1h + dg0 * K1P + kk + 8);
                unsigned ah3 = ld32(A1h + (dg0 + 8) * K1P + kk + 8);
                unsigned al0 = ld32(A1l + dg0 * K1P + kk);
                unsigned al1 = ld32(A1l + (dg0 + 8) * K1P + kk);
                unsigned al2 = ld32(A1l + dg0 * K1P + kk + 8);
                unsigned al3 = ld32(A1l + (dg0 + 8) * K1P + kk + 8);
#pragma unroll
                for (int j = 0; j < 4; j++) {
                    int xc = nw * 32 + j * 8 + qr;
                    unsigned bh0 = ld32(B1h + xc * K1P + kk);
                    unsigned bh1 = ld32(B1h + xc * K1P + kk + 8);
                    unsigned bl0 = ld32(B1l + xc * K1P + kk);
                    unsigned bl1 = ld32(B1l + xc * K1P + kk + 8);
                    mma_bf16(c1[j], ah0, ah1, ah2, ah3, bh0, bh1);
                    mma_bf16(c1[j], ah0, ah1, ah2, ah3, bl0, bl1);
                    mma_bf16(c1[j], al0, al1, al2, al3, bh0, bh1);
                }
            }
#pragma unroll
            for (int j = 0; j < 4; j++) {
                int xc = nw * 32 + j * 8 + qc * 2;
                float v0 = gelu_f(c1[j][0]), v1 = gelu_f(c1[j][1]);
                float v2 = gelu_f(c1[j][2]), v3 = gelu_f(c1[j][3]);
                split_bf(v0, Hh[xc * HP + r0],           Hl[xc * HP + r0]);
                split_bf(v1, Hh[(xc + 1) * HP + r0],     Hl[(xc + 1) * HP + r0]);
                split_bf(v2, Hh[xc * HP + r0 + 8],       Hl[xc * HP + r0 + 8]);
                split_bf(v3, Hh[(xc + 1) * HP + r0 + 8], Hl[(xc + 1) * HP + r0 + 8]);
            }
            __syncthreads();
#pragma unroll
            for (int k0 = 0; k0 < 2; k0++) {
                int kk = k0 * 16 + qc * 2;
                int kg = chunk * 32 + kk;
                unsigned ah0 = ld32(A2h + r0 * K2P + kg);
                unsigned ah1 = ld32(A2h + (r0 + 8) * K2P + kg);
                unsigned ah2 = ld32(A2h + r0 * K2P + kg + 8);
                unsigned ah3 = ld32(A2h + (r0 + 8) * K2P + kg + 8);
                unsigned al0 = ld32(A2l + r0 * K2P + kg);
                unsigned al1 = ld32(A2l + (r0 + 8) * K2P + kg);
                unsigned al2 = ld32(A2l + r0 * K2P + kg + 8);
                unsigned al3 = ld32(A2l + (r0 + 8) * K2P + kg + 8);
#pragma unroll
                for (int j = 0; j < 4; j++) {
                    int xc = nw * 32 + j * 8 + qr;
                    unsigned bh0 = ld32(Hh + xc * HP + kk);
                    unsigned bh1 = ld32(Hh + xc * HP + kk + 8);
                    unsigned bl0 = ld32(Hl + xc * HP + kk);
                    unsigned bl1 = ld32(Hl + xc * HP + kk + 8);
                    mma_bf16(c2[j], ah0, ah1, ah2, ah3, bh0, bh1);
                    mma_bf16(c2[j], ah0, ah1, ah2, ah3, bl0, bl1);
                    mma_bf16(c2[j], al0, al1, al2, al3, bh0, bh1);
                }
            }
            __syncthreads();
        }

        int e0 = r0, e1 = r0 + 8;
#pragma unroll
        for (int j = 0; j < 4; j++) {
            int xc = nh * 128 + nw * 32 + j * 8 + qc * 2;
            if (e0 < COUTC) {
                *(float2*)(out + (bb * COUTC + e0) * NPIX + y * 256 + xc) =
                    make_float2(c2[j][0] + b2s[e0], c2[j][1] + b2s[e0]);
            }
            if (e1 < COUTC) {
                *(float2*)(out + (bb * COUTC + e1) * NPIX + y * 256 + xc) =
                    make_float2(c2[j][2] + b2s[e1], c2[j][3] + b2s[e1]);
            }
        }
    }
}

// ---------------- launch ------------------------------------------------------
extern "C" void kernel_launch(void* const* d_in, const int* in_sizes, int n_in,
                              void* d_out, int out_size) {
    const float* x    = (const float*)d_in[0];
    const float* w1r  = (const float*)d_in[1];
    const float* w1i  = (const float*)d_in[2];
    const float* w2r  = (const float*)d_in[3];
    const float* w2i  = (const float*)d_in[4];
    const float* pw_w = (const float*)d_in[5];
    const float* pw_b = (const float*)d_in[6];
    const float* fc0w = (const float*)d_in[7];
    const float* fc0b = (const float*)d_in[8];
    const float* fc1w = (const float*)d_in[9];
    const float* fc1b = (const float*)d_in[10];
    const float* fc2w = (const float*)d_in[11];
    const float* fc2b = (const float*)d_in[12];
    float* out = (float*)d_out;

    cudaFuncSetAttribute(k_fuse_mma, cudaFuncAttributeMaxDynamicSharedMemorySize, FUSE2_SMEM);
    cudaFuncSetAttribute(k_lift_gx, cudaFuncAttributeMaxDynamicSharedMemorySize, LIFT_SMEM);
    cudaFuncSetAttribute(k_fwdY_mma, cudaFuncAttributeMaxDynamicSharedMemorySize, FWDY2_SMEM);
    cudaFuncSetAttribute(k_invY_mma, cudaFuncAttributeMaxDynamicSharedMemorySize, INVY2_SMEM);
    cudaFuncSetAttribute(k_head_mma, cudaFuncAttributeMaxDynamicSharedMemorySize, HEAD3_SMEM);

    k_init_basis<<<32, 256>>>();
    k_wsplit_fc0<<<8, 256>>>(fc0w);
    k_wtrans<<<512, 256>>>(w1r, w1i, w2r, w2i);
    k_lift_gx<<<4096, 256, LIFT_SMEM>>>(x, fc0b);   // MMA lift + layer-0 Gx
    for (int l = 0; l < NL; l++) {
        k_fwdY_mma<<<1024, 256, FWDY2_SMEM>>>();
        k_mix<<<512, 256>>>(l);
        k_invY_mma<<<1024, 256, INVY2_SMEM>>>();
        k_fuse_mma<<<4096, 256, FUSE2_SMEM>>>(pw_w, pw_b, l, (l < NL - 1) ? 1 : 0);
    }
    k_head_mma<<<4096, 256, HEAD3_SMEM>>>(fc1w, fc1b, fc2w, fc2b, out);
}